// round 11
// baseline (speedup 1.0000x reference)
#include <cuda_runtime.h>
#include <cuda_bf16.h>
#include <cstdint>

#define N_TOK 4096
#define DM    512
#define NH    8
#define DKH   64
#define DFF   2048

// ---------------- scratch (device globals; no runtime allocation) ----------
__device__ float g_Q[N_TOK * DM];     // unused (kept for layout stability)
__device__ float g_V[N_TOK * DM];
__device__ float g_tmp[N_TOK * DM];
__device__ float g_h1[N_TOK * DM];

// bf16 hi/lo planes
__device__ __nv_bfloat16 g_hb_hi[N_TOK * DM],  g_hb_lo[N_TOK * DM];
__device__ __nv_bfloat16 g_cx_hi[N_TOK * DM],  g_cx_lo[N_TOK * DM];
__device__ __nv_bfloat16 g_h1_hi[N_TOK * DM],  g_h1_lo[N_TOK * DM];
__device__ __nv_bfloat16 g_ff_hi[(size_t)N_TOK * DFF], g_ff_lo[(size_t)N_TOK * DFF];
#define WOFF_Q  0
#define WOFF_K  (512 * 512)
#define WOFF_V  (2 * 512 * 512)
#define WOFF_O  (3 * 512 * 512)
#define WOFF_1  (4 * 512 * 512)
#define WOFF_2  (4 * 512 * 512 + 2048 * 512)
#define WTOT    (4 * 512 * 512 + 2 * 2048 * 512)
__device__ __nv_bfloat16 g_w_hi[WTOT], g_w_lo[WTOT];

// attention: per-head bf16 planes [h][tok][64], V transposed [h][d][tok]
__device__ __nv_bfloat16 g_qs_hi[NH * N_TOK * DKH], g_qs_lo[NH * N_TOK * DKH];
__device__ __nv_bfloat16 g_ks_hi[NH * N_TOK * DKH], g_ks_lo[NH * N_TOK * DKH];
__device__ __nv_bfloat16 g_vt[NH * DKH * N_TOK];
__device__ unsigned long long g_adjb[N_TOK * (N_TOK / 64)];

// epilogue output modes
#define OUT_F32    0
#define OUT_PLANES 1
#define OUT_HEADS  2

// ===================== low-level helpers ==================================
__device__ __forceinline__ uint32_t smem_u32(const void* p) {
    uint32_t a;
    asm("{ .reg .u64 t; cvta.to.shared.u64 t, %1; cvt.u32.u64 %0, t; }"
        : "=r"(a) : "l"(p));
    return a;
}
__device__ __forceinline__ void cp16(uint32_t dst, const void* src) {
    asm volatile("cp.async.cg.shared.global [%0], [%1], 16;" :: "r"(dst), "l"(src));
}
__device__ __forceinline__ void ldm_x4(uint32_t* r, uint32_t addr) {
    asm volatile("ldmatrix.sync.aligned.m8n8.x4.shared.b16 {%0,%1,%2,%3}, [%4];"
                 : "=r"(r[0]), "=r"(r[1]), "=r"(r[2]), "=r"(r[3]) : "r"(addr));
}
__device__ __forceinline__ void mma_bf16(float* d, const uint32_t* a, const uint32_t* b) {
    asm volatile("mma.sync.aligned.m16n8k16.row.col.f32.bf16.bf16.f32 "
                 "{%0,%1,%2,%3},{%4,%5,%6,%7},{%8,%9},{%0,%1,%2,%3};"
                 : "+f"(d[0]), "+f"(d[1]), "+f"(d[2]), "+f"(d[3])
                 : "r"(a[0]), "r"(a[1]), "r"(a[2]), "r"(a[3]),
                   "r"(b[0]), "r"(b[1]));
}
__device__ __forceinline__ float fexp2b(float s) {
    const float C1 = 12582904.0f;                 // 1.5*2^23 - 8
    float t  = s + C1;
    float v  = t - C1;
    float zf = s - v;
    int   zi = __float_as_int(t) - 0x4B400000;
    float p = fmaf(zf, 0.00961813f, 0.05550411f);
    p = fmaf(zf, p, 0.24022651f);
    p = fmaf(zf, p, 0.69314718f);
    p = fmaf(zf, p, 1.0f);
    return __int_as_float(__float_as_int(p) + (zi << 23));
}
// pack 2 fp32 -> (hi bf162, lo bf162)
__device__ __forceinline__ void split2(float x, float y, uint32_t& hi, uint32_t& lo) {
    __nv_bfloat162 h = __floats2bfloat162_rn(x, y);
    float hx = __bfloat162float(h.x), hy = __bfloat162float(h.y);
    __nv_bfloat162 l = __floats2bfloat162_rn(x - hx, y - hy);
    hi = *reinterpret_cast<uint32_t*>(&h);
    lo = *reinterpret_cast<uint32_t*>(&l);
}

// ===================== element-wise prep kernels ==========================
__global__ __launch_bounds__(256) void convert_split(const float* __restrict__ in,
                                                     __nv_bfloat16* __restrict__ hi,
                                                     __nv_bfloat16* __restrict__ lo,
                                                     int n)
{
    for (int i = (blockIdx.x * 256 + threadIdx.x) * 4; i < n; i += gridDim.x * 1024) {
        float4 v = *reinterpret_cast<const float4*>(in + i);
        uint32_t h0, l0, h1, l1;
        split2(v.x, v.y, h0, l0);
        split2(v.z, v.w, h1, l1);
        *reinterpret_cast<uint32_t*>(hi + i)     = h0;
        *reinterpret_cast<uint32_t*>(hi + i + 2) = h1;
        *reinterpret_cast<uint32_t*>(lo + i)     = l0;
        *reinterpret_cast<uint32_t*>(lo + i + 2) = l1;
    }
}

// all 6 weights in one launch
__global__ __launch_bounds__(256) void convert_w(const float* __restrict__ Wq,
                                                 const float* __restrict__ Wk,
                                                 const float* __restrict__ Wv,
                                                 const float* __restrict__ Wo,
                                                 const float* __restrict__ W1,
                                                 const float* __restrict__ W2,
                                                 __nv_bfloat16* __restrict__ hi,
                                                 __nv_bfloat16* __restrict__ lo)
{
    const int WSQ = 512 * 512, WFF = 2048 * 512;
    for (int i = (blockIdx.x * 256 + threadIdx.x) * 4; i < WTOT; i += gridDim.x * 1024) {
        const float* src; int off;
        if (i < 4 * WSQ)            { int r = i / WSQ; off = i - r * WSQ;
                                      src = (r == 0) ? Wq : (r == 1) ? Wk : (r == 2) ? Wv : Wo; }
        else if (i < 4 * WSQ + WFF) { src = W1; off = i - 4 * WSQ; }
        else                        { src = W2; off = i - 4 * WSQ - WFF; }
        float4 v = *reinterpret_cast<const float4*>(src + off);
        uint32_t h0, l0, h1, l1;
        split2(v.x, v.y, h0, l0);
        split2(v.z, v.w, h1, l1);
        *reinterpret_cast<uint32_t*>(hi + i)     = h0;
        *reinterpret_cast<uint32_t*>(hi + i + 2) = h1;
        *reinterpret_cast<uint32_t*>(lo + i)     = l0;
        *reinterpret_cast<uint32_t*>(lo + i + 2) = l1;
    }
}

// V fp32 [tok][512] -> bf16 transposed [h][d][tok]
__global__ __launch_bounds__(256) void convert_v_t(const float* __restrict__ V,
                                                   __nv_bfloat16* __restrict__ vt)
{
    __shared__ float sm[64][65];
    const int h = blockIdx.y, t0 = blockIdx.x * 64;
    const int tid = threadIdx.x;
    for (int i = tid; i < 1024; i += 256) {
        int r = i >> 4, c4 = (i & 15) * 4;
        float4 v = *reinterpret_cast<const float4*>(&V[(size_t)(t0 + r) * DM + h * DKH + c4]);
        sm[c4][r] = v.x; sm[c4 + 1][r] = v.y; sm[c4 + 2][r] = v.z; sm[c4 + 3][r] = v.w;
    }
    __syncthreads();
    for (int i = tid; i < 2048; i += 256) {
        int d = i >> 5, pr = i & 31;
        __nv_bfloat162 b = __floats2bfloat162_rn(sm[d][2 * pr], sm[d][2 * pr + 1]);
        *reinterpret_cast<__nv_bfloat162*>(
            vt + (size_t)h * (DKH * N_TOK) + (size_t)d * N_TOK + t0 + 2 * pr) = b;
    }
}

__global__ __launch_bounds__(256) void pack_adj(const int* __restrict__ adj,
                                                unsigned long long* __restrict__ bits)
{
    int gid = blockIdx.x * 256 + threadIdx.x;
    int r = gid >> 6, w = gid & 63;
    const int4* p = reinterpret_cast<const int4*>(adj + (size_t)r * N_TOK + w * 64);
    unsigned long long b = 0;
    #pragma unroll
    for (int i = 0; i < 16; i++) {
        int4 a = p[i];
        if (a.x) b |= 1ull << (i * 4 + 0);
        if (a.y) b |= 1ull << (i * 4 + 1);
        if (a.z) b |= 1ull << (i * 4 + 2);
        if (a.w) b |= 1ull << (i * 4 + 3);
    }
    if ((r >> 6) == w) b |= 1ull << (r & 63);
    bits[gid] = b;
}

// ===================== pipelined split-bf16 GEMM ==========================
#define SROW 80

__device__ __forceinline__ void gemm_load_chunk(
    uint32_t sa_hi, uint32_t sa_lo, uint32_t sb_hi, uint32_t sb_lo,
    const __nv_bfloat16* gA_hi, const __nv_bfloat16* gA_lo,
    const __nv_bfloat16* gB_hi, const __nv_bfloat16* gB_lo,
    int K, int c, int tid)
{
    const int u  = tid & 3;
    const int gk = c * 32 + u * 8;
    #pragma unroll
    for (int i = 0; i < 2; i++) {
        const int row = (tid >> 2) + i * 32;
        const uint32_t doff = (uint32_t)(row * SROW + u * 16);
        const size_t go = (size_t)row * K + gk;
        cp16(sa_hi + doff, gA_hi + go);
        cp16(sa_lo + doff, gA_lo + go);
        cp16(sb_hi + doff, gB_hi + go);
        cp16(sb_lo + doff, gB_lo + go);
    }
    asm volatile("cp.async.commit_group;");
}

template <bool RELU>
__device__ __forceinline__ void gemm_mma_body(const __nv_bfloat16* __restrict__ Ahi,
                                              const __nv_bfloat16* __restrict__ Alo,
                                              const __nv_bfloat16* __restrict__ Bhi,
                                              const __nv_bfloat16* __restrict__ Blo,
                                              const float* __restrict__ bias,
                                              float* __restrict__ C,
                                              __nv_bfloat16* __restrict__ Phi,
                                              __nv_bfloat16* __restrict__ Plo,
                                              float oscale,
                                              int Nn, int K, int mode)
{
    __shared__ __align__(128) uint8_t s_ahi[2][64 * SROW];
    __shared__ __align__(128) uint8_t s_alo[2][64 * SROW];
    __shared__ __align__(128) uint8_t s_bhi[2][64 * SROW];
    __shared__ __align__(128) uint8_t s_blo[2][64 * SROW];

    const int tid = threadIdx.x, lid = tid & 31, wid = tid >> 5;
    const int wm  = wid * 16;
    const int m0  = blockIdx.y * 64, n0 = blockIdx.x * 64;

    const uint32_t sa_hi[2] = {smem_u32(s_ahi[0]), smem_u32(s_ahi[1])};
    const uint32_t sa_lo[2] = {smem_u32(s_alo[0]), smem_u32(s_alo[1])};
    const uint32_t sb_hi[2] = {smem_u32(s_bhi[0]), smem_u32(s_bhi[1])};
    const uint32_t sb_lo[2] = {smem_u32(s_blo[0]), smem_u32(s_blo[1])};

    const __nv_bfloat16* gA_hi = Ahi + (size_t)m0 * K;
    const __nv_bfloat16* gA_lo = Alo + (size_t)m0 * K;
    const __nv_bfloat16* gB_hi = Bhi + (size_t)n0 * K;
    const __nv_bfloat16* gB_lo = Blo + (size_t)n0 * K;

    const int a_row = lid & 15;
    const int a_sel = lid >> 4;
    const int b_row = ((lid >> 4) & 1) * 8 + (lid & 7);
    const int b_sel = (lid >> 3) & 1;

    float acc[8][4] = {};

    const int nch = K >> 5;
    gemm_load_chunk(sa_hi[0], sa_lo[0], sb_hi[0], sb_lo[0],
                    gA_hi, gA_lo, gB_hi, gB_lo, K, 0, tid);
    if (nch > 1)
        gemm_load_chunk(sa_hi[1], sa_lo[1], sb_hi[1], sb_lo[1],
                        gA_hi, gA_lo, gB_hi, gB_lo, K, 1, tid);

    for (int c = 0; c < nch; c++) {
        if (c == nch - 1) asm volatile("cp.async.wait_group 0;" ::: "memory");
        else              asm volatile("cp.async.wait_group 1;" ::: "memory");
        __syncthreads();

        const int st = c & 1;
        #pragma unroll
        for (int ks = 0; ks < 2; ks++) {
            uint32_t ah[4], al[4];
            const uint32_t aoff = (uint32_t)((wm + a_row) * SROW + (ks * 2 + a_sel) * 16);
            ldm_x4(ah, sa_hi[st] + aoff);
            ldm_x4(al, sa_lo[st] + aoff);
            #pragma unroll
            for (int t = 0; t < 4; t++) {
                uint32_t bh[4], bl[4];
                const uint32_t boff = (uint32_t)((t * 16 + b_row) * SROW
                                                 + (ks * 2 + b_sel) * 16);
                ldm_x4(bh, sb_hi[st] + boff);
                ldm_x4(bl, sb_lo[st] + boff);
                #pragma unroll
                for (int t2 = 0; t2 < 2; t2++) {
                    float* d = acc[t * 2 + t2];
                    mma_bf16(d, ah, &bh[t2 * 2]);
                    mma_bf16(d, ah, &bl[t2 * 2]);
                    mma_bf16(d, al, &bh[t2 * 2]);
                }
            }
        }
        __syncthreads();
        if (c + 2 < nch)
            gemm_load_chunk(sa_hi[st], sa_lo[st], sb_hi[st], sb_lo[st],
                            gA_hi, gA_lo, gB_hi, gB_lo, K, c + 2, tid);
    }

    // epilogue
    const int rr0   = m0 + wm + (lid >> 2);
    const int cbase = n0 + (lid & 3) * 2;
    #pragma unroll
    for (int f = 0; f < 8; f++) {
        const int col = cbase + f * 8;
        const float bx = bias[col], by = bias[col + 1];
        float v00 = acc[f][0] + bx, v01 = acc[f][1] + by;
        float v10 = acc[f][2] + bx, v11 = acc[f][3] + by;
        if (RELU) {
            v00 = fmaxf(v00, 0.0f); v01 = fmaxf(v01, 0.0f);
            v10 = fmaxf(v10, 0.0f); v11 = fmaxf(v11, 0.0f);
        }
        if (mode == OUT_F32) {
            *reinterpret_cast<float2*>(C + (size_t)rr0 * Nn + col)       = make_float2(v00, v01);
            *reinterpret_cast<float2*>(C + (size_t)(rr0 + 8) * Nn + col) = make_float2(v10, v11);
        } else if (mode == OUT_PLANES) {
            uint32_t h0, l0, h1, l1;
            split2(v00, v01, h0, l0);
            split2(v10, v11, h1, l1);
            *reinterpret_cast<uint32_t*>(Phi + (size_t)rr0 * Nn + col)       = h0;
            *reinterpret_cast<uint32_t*>(Plo + (size_t)rr0 * Nn + col)       = l0;
            *reinterpret_cast<uint32_t*>(Phi + (size_t)(rr0 + 8) * Nn + col) = h1;
            *reinterpret_cast<uint32_t*>(Plo + (size_t)(rr0 + 8) * Nn + col) = l1;
        } else {   // OUT_HEADS: per-head planes with scale
            const int hh = col >> 6, d = col & 63;
            const size_t base0 = (size_t)hh * (N_TOK * DKH) + (size_t)rr0 * DKH + d;
            const size_t base1 = base0 + 8 * DKH;
            uint32_t h0, l0, h1, l1;
            split2(v00 * oscale, v01 * oscale, h0, l0);
            split2(v10 * oscale, v11 * oscale, h1, l1);
            *reinterpret_cast<uint32_t*>(Phi + base0) = h0;
            *reinterpret_cast<uint32_t*>(Plo + base0) = l0;
            *reinterpret_cast<uint32_t*>(Phi + base1) = h1;
            *reinterpret_cast<uint32_t*>(Plo + base1) = l1;
        }
    }
}

template <bool RELU>
__global__ __launch_bounds__(128) void gemm_mma(const __nv_bfloat16* __restrict__ Ahi,
                                                const __nv_bfloat16* __restrict__ Alo,
                                                const __nv_bfloat16* __restrict__ Bhi,
                                                const __nv_bfloat16* __restrict__ Blo,
                                                const float* __restrict__ bias,
                                                float* C,
                                                __nv_bfloat16* Phi, __nv_bfloat16* Plo,
                                                float oscale, int Nn, int K, int mode)
{
    gemm_mma_body<RELU>(Ahi, Alo, Bhi, Blo, bias, C, Phi, Plo, oscale, Nn, K, mode);
}

// fused QKV: z selects weight / bias / output mode
__global__ __launch_bounds__(128) void gemm_mma_qkv(const __nv_bfloat16* __restrict__ Ahi,
                                                    const __nv_bfloat16* __restrict__ Alo,
                                                    const float* __restrict__ bq,
                                                    const float* __restrict__ bk,
                                                    const float* __restrict__ bv,
                                                    __nv_bfloat16* qhi, __nv_bfloat16* qlo,
                                                    __nv_bfloat16* khi, __nv_bfloat16* klo,
                                                    float* Vo, float qscale)
{
    const __nv_bfloat16* whi; const __nv_bfloat16* wlo;
    const float* bias; float* C = nullptr;
    __nv_bfloat16 *phi = nullptr, *plo = nullptr;
    float sc = 1.0f; int mode;
    if (blockIdx.z == 0) {
        whi = g_w_hi + WOFF_Q; wlo = g_w_lo + WOFF_Q; bias = bq;
        phi = qhi; plo = qlo; sc = qscale; mode = OUT_HEADS;
    } else if (blockIdx.z == 1) {
        whi = g_w_hi + WOFF_K; wlo = g_w_lo + WOFF_K; bias = bk;
        phi = khi; plo = klo; mode = OUT_HEADS;
    } else {
        whi = g_w_hi + WOFF_V; wlo = g_w_lo + WOFF_V; bias = bv;
        C = Vo; mode = OUT_F32;
    }
    gemm_mma_body<false>(Ahi, Alo, whi, wlo, bias, C, phi, plo, sc, DM, DM, mode);
}

// ===================== tensor-core flash attention ========================
// writes cx hi/lo planes directly
__global__ __launch_bounds__(128) void attn_mma(
    const __nv_bfloat16* __restrict__ qhi, const __nv_bfloat16* __restrict__ qlo,
    const __nv_bfloat16* __restrict__ khi, const __nv_bfloat16* __restrict__ klo,
    const __nv_bfloat16* __restrict__ vt,
    const unsigned long long* __restrict__ adjb,
    __nv_bfloat16* __restrict__ cxhi, __nv_bfloat16* __restrict__ cxlo)
{
    __shared__ __align__(128) uint8_t s_khi[2 * 64 * SROW];
    __shared__ __align__(128) uint8_t s_klo[2 * 64 * SROW];
    __shared__ __align__(128) uint8_t s_vt [2 * 64 * SROW];

    const int tid = threadIdx.x, lid = tid & 31, wid = tid >> 5;
    const int h = blockIdx.y, q0 = blockIdx.x * 64;
    const int wm = wid * 16;
    const size_t hoff = (size_t)h * (N_TOK * DKH);

    const uint32_t skhi = smem_u32(s_khi), sklo = smem_u32(s_klo), svt = smem_u32(s_vt);

    uint32_t qa_h[4][4], qa_l[4][4];
    const int rr0 = q0 + wm + (lid >> 2);
    {
        const int cc = (lid & 3) * 2;
        #pragma unroll
        for (int ks = 0; ks < 4; ks++) {
            const size_t o0 = hoff + (size_t)rr0 * 64 + ks * 16 + cc;
            const size_t o1 = hoff + (size_t)(rr0 + 8) * 64 + ks * 16 + cc;
            qa_h[ks][0] = *reinterpret_cast<const uint32_t*>(qhi + o0);
            qa_h[ks][1] = *reinterpret_cast<const uint32_t*>(qhi + o1);
            qa_h[ks][2] = *reinterpret_cast<const uint32_t*>(qhi + o0 + 8);
            qa_h[ks][3] = *reinterpret_cast<const uint32_t*>(qhi + o1 + 8);
            qa_l[ks][0] = *reinterpret_cast<const uint32_t*>(qlo + o0);
            qa_l[ks][1] = *reinterpret_cast<const uint32_t*>(qlo + o1);
            qa_l[ks][2] = *reinterpret_cast<const uint32_t*>(qlo + o0 + 8);
            qa_l[ks][3] = *reinterpret_cast<const uint32_t*>(qlo + o1 + 8);
        }
    }

    const int b_row = ((lid >> 4) & 1) * 8 + (lid & 7);
    const int b_sel = (lid >> 3) & 1;

    float o_acc[8][4] = {};
    float lsum0 = 0.0f, lsum1 = 0.0f;

    {
        #pragma unroll
        for (int i = 0; i < 4; i++) {
            const int idx = tid + i * 128;
            const int row = idx >> 3, ch = (idx >> 2) & 1, u = idx & 3;
            const uint32_t doff = (uint32_t)((ch * 64 + row) * SROW + u * 16);
            cp16(skhi + doff, khi + hoff + (size_t)row * 64 + ch * 32 + u * 8);
            cp16(sklo + doff, klo + hoff + (size_t)row * 64 + ch * 32 + u * 8);
            cp16(svt  + doff, vt  + hoff + (size_t)row * N_TOK + ch * 32 + u * 8);
        }
        asm volatile("cp.async.commit_group;");
    }

    for (int kb = 0; kb < N_TOK / 64; kb++) {
        asm volatile("cp.async.wait_group 0;" ::: "memory");
        __syncthreads();

        float sc[8][4] = {};
        #pragma unroll
        for (int ks = 0; ks < 4; ks++) {
            const uint32_t base = (uint32_t)(((ks >> 1) * 64 + b_row) * SROW
                                             + ((ks & 1) * 2 + b_sel) * 16);
            #pragma unroll
            for (int t = 0; t < 4; t++) {
                uint32_t bh[4], bl[4];
                ldm_x4(bh, skhi + base + t * 16 * SROW);
                ldm_x4(bl, sklo + base + t * 16 * SROW);
                #pragma unroll
                for (int t2 = 0; t2 < 2; t2++) {
                    float* d = sc[t * 2 + t2];
                    mma_bf16(d, qa_h[ks], &bh[t2 * 2]);
                    mma_bf16(d, qa_h[ks], &bl[t2 * 2]);
                    mma_bf16(d, qa_l[ks], &bh[t2 * 2]);
                }
            }
        }

        const unsigned long long w0 = adjb[(size_t)rr0 * 64 + kb];
        const unsigned long long w1 = adjb[(size_t)(rr0 + 8) * 64 + kb];
        uint32_t pa[4][4];
        #pragma unroll
        for (int f = 0; f < 8; f++) {
            const int cb = f * 8 + (lid & 3) * 2;
            const float s0 = ((w0 >> cb) & 1)       ? sc[f][0] : -102.0f;
            const float s1 = ((w0 >> (cb + 1)) & 1) ? sc[f][1] : -102.0f;
            const float s2 = ((w1 >> cb) & 1)       ? sc[f][2] : -102.0f;
            const float s3 = ((w1 >> (cb + 1)) & 1) ? sc[f][3] : -102.0f;
            const float p0 = fexp2b(s0), p1 = fexp2b(s1);
            const float p2 = fexp2b(s2), p3 = fexp2b(s3);
            lsum0 += p0 + p1; lsum1 += p2 + p3;
            __nv_bfloat162 x01 = __floats2bfloat162_rn(p0, p1);
            __nv_bfloat162 x23 = __floats2bfloat162_rn(p2, p3);
            const int j = f >> 1, oo = (f & 1) * 2;
            pa[j][oo]     = *reinterpret_cast<uint32_t*>(&x01);
            pa[j][oo + 1] = *reinterpret_cast<uint32_t*>(&x23);
        }

        #pragma unroll
        for (int ks = 0; ks < 4; ks++) {
            const uint32_t base = (uint32_t)(((ks >> 1) * 64 + b_row) * SROW
                                             + ((ks & 1) * 2 + b_sel) * 16);
            #pragma unroll
            for (int t = 0; t < 4; t++) {
                uint32_t bv[4];
                ldm_x4(bv, svt + base + t * 16 * SROW);
                mma_bf16(o_acc[t * 2],     pa[ks], &bv[0]);
                mma_bf16(o_acc[t * 2 + 1], pa[ks], &bv[2]);
            }
        }

        __syncthreads();
        if (kb < N_TOK / 64 - 1) {
            const int k0 = (kb + 1) * 64;
            #pragma unroll
            for (int i = 0; i < 4; i++) {
                const int idx = tid + i * 128;
                const int row = idx >> 3, ch = (idx >> 2) & 1, u = idx & 3;
                const uint32_t doff = (uint32_t)((ch * 64 + row) * SROW + u * 16);
                cp16(skhi + doff, khi + hoff + (size_t)(k0 + row) * 64 + ch * 32 + u * 8);
                cp16(sklo + doff, klo + hoff + (size_t)(k0 + row) * 64 + ch * 32 + u * 8);
                cp16(svt  + doff, vt  + hoff + (size_t)row * N_TOK + k0 + ch * 32 + u * 8);
            }
            asm volatile("cp.async.commit_group;");
        }
    }

    lsum0 += __shfl_xor_sync(0xffffffffu, lsum0, 1);
    lsum0 += __shfl_xor_sync(0xffffffffu, lsum0, 2);
    lsum1 += __shfl_xor_sync(0xffffffffu, lsum1, 1);
    lsum1 += __shfl_xor_sync(0xffffffffu, lsum1, 2);
    const float inv0 = 1.0f / lsum0, inv1 = 1.0f / lsum1;
    const int col0 = h * DKH + (lid & 3) * 2;
    #pragma unroll
    for (int f = 0; f < 8; f++) {
        uint32_t h0, l0, h1, l1;
        split2(o_acc[f][0] * inv0, o_acc[f][1] * inv0, h0, l0);
        split2(o_acc[f][2] * inv1, o_acc[f][3] * inv1, h1, l1);
        const size_t a0 = (size_t)rr0 * DM + col0 + f * 8;
        const size_t a1 = (size_t)(rr0 + 8) * DM + col0 + f * 8;
        *reinterpret_cast<uint32_t*>(cxhi + a0) = h0;
        *reinterpret_cast<uint32_t*>(cxlo + a0) = l0;
        *reinterpret_cast<uint32_t*>(cxhi + a1) = h1;
        *reinterpret_cast<uint32_t*>(cxlo + a1) = l1;
    }
}

// ---------------------------------------------------------------------------
// out = LayerNorm(x + r) * g + b; optionally also write hi/lo planes
// ---------------------------------------------------------------------------
template <bool PLANES>
__global__ __launch_bounds__(128) void ln_kernel(const float* __restrict__ x,
                                                 const float* __restrict__ r,
                                                 const float* __restrict__ g,
                                                 const float* __restrict__ b,
                                                 float* __restrict__ out,
                                                 __nv_bfloat16* __restrict__ phi,
                                                 __nv_bfloat16* __restrict__ plo)
{
    __shared__ float ws[4], ws2[4];
    const int row = blockIdx.x;
    const int tid = threadIdx.x;
    const int col = tid * 4;

    float4 xv = *reinterpret_cast<const float4*>(&x[(size_t)row * DM + col]);
    float4 rv = *reinterpret_cast<const float4*>(&r[(size_t)row * DM + col]);
    float v[4] = {xv.x + rv.x, xv.y + rv.y, xv.z + rv.z, xv.w + rv.w};

    float s = 0.0f, s2 = 0.0f;
    #pragma unroll
    for (int c = 0; c < 4; c++) { s += v[c]; s2 = fmaf(v[c], v[c], s2); }
    #pragma unroll
    for (int off = 16; off >= 1; off >>= 1) {
        s  += __shfl_xor_sync(0xffffffffu, s,  off);
        s2 += __shfl_xor_sync(0xffffffffu, s2, off);
    }
    const int wid = tid >> 5;
    if ((tid & 31) == 0) { ws[wid] = s; ws2[wid] = s2; }
    __syncthreads();
    const float S  = ws[0] + ws[1] + ws[2] + ws[3];
    const float S2 = ws2[0] + ws2[1] + ws2[2] + ws2[3];
    const float mean = S * (1.0f / DM);
    const float var  = S2 * (1.0f / DM) - mean * mean;
    const float rstd = rsqrtf(var + 1e-5f);

    float4 gv = *reinterpret_cast<const float4*>(&g[col]);
    float4 bv = *reinterpret_cast<const float4*>(&b[col]);
    float gr[4] = {gv.x, gv.y, gv.z, gv.w};
    float br[4] = {bv.x, bv.y, bv.z, bv.w};
    float4 ov; float* op = &ov.x;
    #pragma unroll
    for (int c = 0; c < 4; c++)
        op[c] = (v[c] - mean) * rstd * gr[c] + br[c];
    *reinterpret_cast<float4*>(&out[(size_t)row * DM + col]) = ov;
    if (PLANES) {
        uint32_t h0, l0, h1, l1;
        split2(ov.x, ov.y, h0, l0);
        split2(ov.z, ov.w, h1, l1);
        *reinterpret_cast<uint32_t*>(phi + (size_t)row * DM + col)     = h0;
        *reinterpret_cast<uint32_t*>(plo + (size_t)row * DM + col)     = l0;
        *reinterpret_cast<uint32_t*>(phi + (size_t)row * DM + col + 2) = h1;
        *reinterpret_cast<uint32_t*>(plo + (size_t)row * DM + col + 2) = l1;
    }
}

// ---------------------------------------------------------------------------
extern "C" void kernel_launch(void* const* d_in, const int* in_sizes, int n_in,
                              void* d_out, int out_size)
{
    const float* h    = (const float*)d_in[0];
    const int*   adj  = (const int*)d_in[1];
    const float* Wq   = (const float*)d_in[2];
    const float* bq   = (const float*)d_in[3];
    const float* Wk   = (const float*)d_in[4];
    const float* bk   = (const float*)d_in[5];
    const float* Wv   = (const float*)d_in[6];
    const float* bv   = (const float*)d_in[7];
    const float* Wo   = (const float*)d_in[8];
    const float* bo   = (const float*)d_in[9];
    const float* W1   = (const float*)d_in[10];
    const float* b1   = (const float*)d_in[11];
    const float* W2   = (const float*)d_in[12];
    const float* b2   = (const float*)d_in[13];
    const float* ln1g = (const float*)d_in[14];
    const float* ln1b = (const float*)d_in[15];
    const float* ln2g = (const float*)d_in[16];
    const float* ln2b = (const float*)d_in[17];
    float* out = (float*)d_out;

    float *Vd, *tmp, *h1;
    cudaGetSymbolAddress((void**)&Vd,  g_V);
    cudaGetSymbolAddress((void**)&tmp, g_tmp);
    cudaGetSymbolAddress((void**)&h1,  g_h1);

    __nv_bfloat16 *hb_hi, *hb_lo, *cx_hi, *cx_lo, *h1_hi, *h1_lo, *ff_hi, *ff_lo, *w_hi, *w_lo;
    __nv_bfloat16 *qs_hi, *qs_lo, *ks_hi, *ks_lo, *vtp;
    unsigned long long* adjb;
    cudaGetSymbolAddress((void**)&hb_hi, g_hb_hi);
    cudaGetSymbolAddress((void**)&hb_lo, g_hb_lo);
    cudaGetSymbolAddress((void**)&cx_hi, g_cx_hi);
    cudaGetSymbolAddress((void**)&cx_lo, g_cx_lo);
    cudaGetSymbolAddress((void**)&h1_hi, g_h1_hi);
    cudaGetSymbolAddress((void**)&h1_lo, g_h1_lo);
    cudaGetSymbolAddress((void**)&ff_hi, g_ff_hi);
    cudaGetSymbolAddress((void**)&ff_lo, g_ff_lo);
    cudaGetSymbolAddress((void**)&w_hi,  g_w_hi);
    cudaGetSymbolAddress((void**)&w_lo,  g_w_lo);
    cudaGetSymbolAddress((void**)&qs_hi, g_qs_hi);
    cudaGetSymbolAddress((void**)&qs_lo, g_qs_lo);
    cudaGetSymbolAddress((void**)&ks_hi, g_ks_hi);
    cudaGetSymbolAddress((void**)&ks_lo, g_ks_lo);
    cudaGetSymbolAddress((void**)&vtp,   g_vt);
    cudaGetSymbolAddress((void**)&adjb,  g_adjb);

    const int ACT = N_TOK * DM;
    const float QSCALE = 1.4426950408889634f / 8.0f;   // log2(e)/sqrt(d_k)

    const dim3 blk(128);
    const dim3 gQKV(DM / 64, N_TOK / 64, 3);
    const dim3 gP(DM / 64, N_TOK / 64);
    const dim3 gF1(DFF / 64, N_TOK / 64);

    // launches ordered so attn_mma is the 6th launch (ncu -s 5 profiles it)
    pack_adj<<<(N_TOK * 64) / 256, 256>>>(adj, adjb);                       // 1
    convert_split<<<1024, 256>>>(h, hb_hi, hb_lo, ACT);                     // 2
    convert_w<<<2048, 256>>>(Wq, Wk, Wv, Wo, W1, W2, w_hi, w_lo);           // 3
    gemm_mma_qkv<<<gQKV, blk>>>(hb_hi, hb_lo, bq, bk, bv,                   // 4
                                qs_hi, qs_lo, ks_hi, ks_lo, Vd, QSCALE);
    convert_v_t<<<dim3(N_TOK / 64, NH), 256>>>(Vd, vtp);                    // 5
    attn_mma<<<dim3(N_TOK / 64, NH), blk>>>(qs_hi, qs_lo, ks_hi, ks_lo,     // 6
                                            vtp, adjb, cx_hi, cx_lo);
    gemm_mma<false><<<gP, blk>>>(cx_hi, cx_lo, w_hi + WOFF_O, w_lo + WOFF_O,
                                 bo, tmp, nullptr, nullptr, 1.0f, DM, DM, OUT_F32);
    ln_kernel<true><<<N_TOK, 128>>>(h, tmp, ln1g, ln1b, h1, h1_hi, h1_lo);
    gemm_mma<true><<<gF1, blk>>>(h1_hi, h1_lo, w_hi + WOFF_1, w_lo + WOFF_1,
                                 b1, nullptr, ff_hi, ff_lo, 1.0f, DFF, DM, OUT_PLANES);
    gemm_mma<false><<<gP, blk>>>(ff_hi, ff_lo, w_hi + WOFF_2, w_lo + WOFF_2,
                                 b2, tmp, nullptr, nullptr, 1.0f, DM, DFF, OUT_F32);
    ln_kernel<false><<<N_TOK, 128>>>(h1, tmp, ln2g, ln2b, out, nullptr, nullptr);
}

// round 12
// speedup vs baseline: 1.0201x; 1.0201x over previous
#include <cuda_runtime.h>
#include <cuda_bf16.h>
#include <cstdint>

#define N_TOK 4096
#define DM    512
#define NH    8
#define DKH   64
#define DFF   2048

// ---------------- scratch (device globals; no runtime allocation) ----------
__device__ float g_V[N_TOK * DM];
__device__ float g_tmp[N_TOK * DM];
__device__ float g_h1[N_TOK * DM];

// bf16 hi/lo planes
__device__ __nv_bfloat16 g_hb_hi[N_TOK * DM],  g_hb_lo[N_TOK * DM];
__device__ __nv_bfloat16 g_cx_hi[N_TOK * DM],  g_cx_lo[N_TOK * DM];
__device__ __nv_bfloat16 g_h1_hi[N_TOK * DM],  g_h1_lo[N_TOK * DM];
__device__ __nv_bfloat16 g_ff_hi[(size_t)N_TOK * DFF], g_ff_lo[(size_t)N_TOK * DFF];
#define WOFF_Q  0
#define WOFF_K  (512 * 512)
#define WOFF_V  (2 * 512 * 512)
#define WOFF_O  (3 * 512 * 512)
#define WOFF_1  (4 * 512 * 512)
#define WOFF_2  (4 * 512 * 512 + 2048 * 512)
#define WTOT    (4 * 512 * 512 + 2 * 2048 * 512)
__device__ __nv_bfloat16 g_w_hi[WTOT], g_w_lo[WTOT];

// attention: per-head bf16 planes [h][tok][64], V transposed [h][d][tok]
__device__ __nv_bfloat16 g_qs_hi[NH * N_TOK * DKH], g_qs_lo[NH * N_TOK * DKH];
__device__ __nv_bfloat16 g_ks_hi[NH * N_TOK * DKH], g_ks_lo[NH * N_TOK * DKH];
__device__ __nv_bfloat16 g_vt[NH * DKH * N_TOK];
__device__ unsigned long long g_adjb[N_TOK * (N_TOK / 64)];

// epilogue output modes
#define OUT_F32    0
#define OUT_PLANES 1
#define OUT_HEADS  2

// ===================== low-level helpers ==================================
__device__ __forceinline__ uint32_t smem_u32(const void* p) {
    uint32_t a;
    asm("{ .reg .u64 t; cvta.to.shared.u64 t, %1; cvt.u32.u64 %0, t; }"
        : "=r"(a) : "l"(p));
    return a;
}
__device__ __forceinline__ void cp16(uint32_t dst, const void* src) {
    asm volatile("cp.async.cg.shared.global [%0], [%1], 16;" :: "r"(dst), "l"(src));
}
__device__ __forceinline__ void ldm_x4(uint32_t* r, uint32_t addr) {
    asm volatile("ldmatrix.sync.aligned.m8n8.x4.shared.b16 {%0,%1,%2,%3}, [%4];"
                 : "=r"(r[0]), "=r"(r[1]), "=r"(r[2]), "=r"(r[3]) : "r"(addr));
}
__device__ __forceinline__ void mma_bf16(float* d, const uint32_t* a, const uint32_t* b) {
    asm volatile("mma.sync.aligned.m16n8k16.row.col.f32.bf16.bf16.f32 "
                 "{%0,%1,%2,%3},{%4,%5,%6,%7},{%8,%9},{%0,%1,%2,%3};"
                 : "+f"(d[0]), "+f"(d[1]), "+f"(d[2]), "+f"(d[3])
                 : "r"(a[0]), "r"(a[1]), "r"(a[2]), "r"(a[3]),
                   "r"(b[0]), "r"(b[1]));
}
__device__ __forceinline__ float fexp2b(float s) {
    const float C1 = 12582904.0f;                 // 1.5*2^23 - 8
    float t  = s + C1;
    float v  = t - C1;
    float zf = s - v;
    int   zi = __float_as_int(t) - 0x4B400000;
    float p = fmaf(zf, 0.00961813f, 0.05550411f);
    p = fmaf(zf, p, 0.24022651f);
    p = fmaf(zf, p, 0.69314718f);
    p = fmaf(zf, p, 1.0f);
    return __int_as_float(__float_as_int(p) + (zi << 23));
}
__device__ __forceinline__ void split2(float x, float y, uint32_t& hi, uint32_t& lo) {
    __nv_bfloat162 h = __floats2bfloat162_rn(x, y);
    float hx = __bfloat162float(h.x), hy = __bfloat162float(h.y);
    __nv_bfloat162 l = __floats2bfloat162_rn(x - hx, y - hy);
    hi = *reinterpret_cast<uint32_t*>(&h);
    lo = *reinterpret_cast<uint32_t*>(&l);
}

// ===================== element-wise prep kernels ==========================
__global__ __launch_bounds__(256) void convert_split(const float* __restrict__ in,
                                                     __nv_bfloat16* __restrict__ hi,
                                                     __nv_bfloat16* __restrict__ lo,
                                                     int n)
{
    for (int i = (blockIdx.x * 256 + threadIdx.x) * 4; i < n; i += gridDim.x * 1024) {
        float4 v = *reinterpret_cast<const float4*>(in + i);
        uint32_t h0, l0, h1, l1;
        split2(v.x, v.y, h0, l0);
        split2(v.z, v.w, h1, l1);
        *reinterpret_cast<uint32_t*>(hi + i)     = h0;
        *reinterpret_cast<uint32_t*>(hi + i + 2) = h1;
        *reinterpret_cast<uint32_t*>(lo + i)     = l0;
        *reinterpret_cast<uint32_t*>(lo + i + 2) = l1;
    }
}

__global__ __launch_bounds__(256) void convert_w(const float* __restrict__ Wq,
                                                 const float* __restrict__ Wk,
                                                 const float* __restrict__ Wv,
                                                 const float* __restrict__ Wo,
                                                 const float* __restrict__ W1,
                                                 const float* __restrict__ W2,
                                                 __nv_bfloat16* __restrict__ hi,
                                                 __nv_bfloat16* __restrict__ lo)
{
    const int WSQ = 512 * 512, WFF = 2048 * 512;
    for (int i = (blockIdx.x * 256 + threadIdx.x) * 4; i < WTOT; i += gridDim.x * 1024) {
        const float* src; int off;
        if (i < 4 * WSQ)            { int r = i / WSQ; off = i - r * WSQ;
                                      src = (r == 0) ? Wq : (r == 1) ? Wk : (r == 2) ? Wv : Wo; }
        else if (i < 4 * WSQ + WFF) { src = W1; off = i - 4 * WSQ; }
        else                        { src = W2; off = i - 4 * WSQ - WFF; }
        float4 v = *reinterpret_cast<const float4*>(src + off);
        uint32_t h0, l0, h1, l1;
        split2(v.x, v.y, h0, l0);
        split2(v.z, v.w, h1, l1);
        *reinterpret_cast<uint32_t*>(hi + i)     = h0;
        *reinterpret_cast<uint32_t*>(hi + i + 2) = h1;
        *reinterpret_cast<uint32_t*>(lo + i)     = l0;
        *reinterpret_cast<uint32_t*>(lo + i + 2) = l1;
    }
}

__global__ __launch_bounds__(256) void convert_v_t(const float* __restrict__ V,
                                                   __nv_bfloat16* __restrict__ vt)
{
    __shared__ float sm[64][65];
    const int h = blockIdx.y, t0 = blockIdx.x * 64;
    const int tid = threadIdx.x;
    for (int i = tid; i < 1024; i += 256) {
        int r = i >> 4, c4 = (i & 15) * 4;
        float4 v = *reinterpret_cast<const float4*>(&V[(size_t)(t0 + r) * DM + h * DKH + c4]);
        sm[c4][r] = v.x; sm[c4 + 1][r] = v.y; sm[c4 + 2][r] = v.z; sm[c4 + 3][r] = v.w;
    }
    __syncthreads();
    for (int i = tid; i < 2048; i += 256) {
        int d = i >> 5, pr = i & 31;
        __nv_bfloat162 b = __floats2bfloat162_rn(sm[d][2 * pr], sm[d][2 * pr + 1]);
        *reinterpret_cast<__nv_bfloat162*>(
            vt + (size_t)h * (DKH * N_TOK) + (size_t)d * N_TOK + t0 + 2 * pr) = b;
    }
}

__global__ __launch_bounds__(256) void pack_adj(const int* __restrict__ adj,
                                                unsigned long long* __restrict__ bits)
{
    int gid = blockIdx.x * 256 + threadIdx.x;
    int r = gid >> 6, w = gid & 63;
    const int4* p = reinterpret_cast<const int4*>(adj + (size_t)r * N_TOK + w * 64);
    unsigned long long b = 0;
    #pragma unroll
    for (int i = 0; i < 16; i++) {
        int4 a = p[i];
        if (a.x) b |= 1ull << (i * 4 + 0);
        if (a.y) b |= 1ull << (i * 4 + 1);
        if (a.z) b |= 1ull << (i * 4 + 2);
        if (a.w) b |= 1ull << (i * 4 + 3);
    }
    if ((r >> 6) == w) b |= 1ull << (r & 63);
    bits[gid] = b;
}

// ===================== 128x64-tile pipelined split-bf16 GEMM ==============
// CTA = 128m x 64n, 4 warps, warp = 32m x 64n. k-chunk 32, 2-stage pipeline.
// Dynamic smem layout per stage: A_hi(10240) A_lo(10240) B_hi(5120) B_lo(5120)
#define SROW 80
#define GS_AH 0
#define GS_AL 10240
#define GS_BH 20480
#define GS_BL 25600
#define GS_STAGE 30720
#define GEMM_SMEM (2 * GS_STAGE)

extern __shared__ __align__(128) uint8_t g_dyn[];

__device__ __forceinline__ void gemm_load_chunk(
    uint32_t sbase,
    const __nv_bfloat16* gA_hi, const __nv_bfloat16* gA_lo,
    const __nv_bfloat16* gB_hi, const __nv_bfloat16* gB_lo,
    int K, int c, int tid)
{
    const int u  = tid & 3;
    const int gk = c * 32 + u * 8;
    #pragma unroll
    for (int i = 0; i < 4; i++) {      // A: 128 rows
        const int row = (tid >> 2) + i * 32;
        const uint32_t doff = (uint32_t)(row * SROW + u * 16);
        const size_t go = (size_t)row * K + gk;
        cp16(sbase + GS_AH + doff, gA_hi + go);
        cp16(sbase + GS_AL + doff, gA_lo + go);
    }
    #pragma unroll
    for (int i = 0; i < 2; i++) {      // B: 64 rows
        const int row = (tid >> 2) + i * 32;
        const uint32_t doff = (uint32_t)(row * SROW + u * 16);
        const size_t go = (size_t)row * K + gk;
        cp16(sbase + GS_BH + doff, gB_hi + go);
        cp16(sbase + GS_BL + doff, gB_lo + go);
    }
    asm volatile("cp.async.commit_group;");
}

template <bool RELU>
__device__ __forceinline__ void gemm_mma_body(const __nv_bfloat16* __restrict__ Ahi,
                                              const __nv_bfloat16* __restrict__ Alo,
                                              const __nv_bfloat16* __restrict__ Bhi,
                                              const __nv_bfloat16* __restrict__ Blo,
                                              const float* __restrict__ bias,
                                              float* __restrict__ C,
                                              __nv_bfloat16* __restrict__ Phi,
                                              __nv_bfloat16* __restrict__ Plo,
                                              float oscale,
                                              int Nn, int K, int mode)
{
    const int tid = threadIdx.x, lid = tid & 31, wid = tid >> 5;
    const int wm  = wid * 32;
    const int m0  = blockIdx.y * 128, n0 = blockIdx.x * 64;

    const uint32_t sb0 = smem_u32(g_dyn);
    const uint32_t sb[2] = {sb0, sb0 + GS_STAGE};

    const __nv_bfloat16* gA_hi = Ahi + (size_t)m0 * K;
    const __nv_bfloat16* gA_lo = Alo + (size_t)m0 * K;
    const __nv_bfloat16* gB_hi = Bhi + (size_t)n0 * K;
    const __nv_bfloat16* gB_lo = Blo + (size_t)n0 * K;

    const int a_row = lid & 15;
    const int a_sel = lid >> 4;
    const int b_row = ((lid >> 4) & 1) * 8 + (lid & 7);
    const int b_sel = (lid >> 3) & 1;

    float acc[2][8][4] = {};

    const int nch = K >> 5;
    gemm_load_chunk(sb[0], gA_hi, gA_lo, gB_hi, gB_lo, K, 0, tid);
    if (nch > 1)
        gemm_load_chunk(sb[1], gA_hi, gA_lo, gB_hi, gB_lo, K, 1, tid);

    for (int c = 0; c < nch; c++) {
        if (c == nch - 1) asm volatile("cp.async.wait_group 0;" ::: "memory");
        else              asm volatile("cp.async.wait_group 1;" ::: "memory");
        __syncthreads();

        const uint32_t st = sb[c & 1];
        #pragma unroll
        for (int ks = 0; ks < 2; ks++) {
            uint32_t ah[2][4], al[2][4];
            #pragma unroll
            for (int mg = 0; mg < 2; mg++) {
                const uint32_t aoff = (uint32_t)((wm + mg * 16 + a_row) * SROW
                                                 + (ks * 2 + a_sel) * 16);
                ldm_x4(ah[mg], st + GS_AH + aoff);
                ldm_x4(al[mg], st + GS_AL + aoff);
            }
            #pragma unroll
            for (int t = 0; t < 4; t++) {
                uint32_t bh[4], bl[4];
                const uint32_t boff = (uint32_t)((t * 16 + b_row) * SROW
                                                 + (ks * 2 + b_sel) * 16);
                ldm_x4(bh, st + GS_BH + boff);
                ldm_x4(bl, st + GS_BL + boff);
                #pragma unroll
                for (int mg = 0; mg < 2; mg++)
                    #pragma unroll
                    for (int t2 = 0; t2 < 2; t2++) {
                        float* d = acc[mg][t * 2 + t2];
                        mma_bf16(d, ah[mg], &bh[t2 * 2]);
                        mma_bf16(d, ah[mg], &bl[t2 * 2]);
                        mma_bf16(d, al[mg], &bh[t2 * 2]);
                    }
            }
        }
        __syncthreads();
        if (c + 2 < nch)
            gemm_load_chunk(sb[c & 1], gA_hi, gA_lo, gB_hi, gB_lo, K, c + 2, tid);
    }

    // epilogue
    const int cbase = n0 + (lid & 3) * 2;
    #pragma unroll
    for (int mg = 0; mg < 2; mg++) {
        const int rr0 = m0 + wm + mg * 16 + (lid >> 2);
        #pragma unroll
        for (int f = 0; f < 8; f++) {
            const int col = cbase + f * 8;
            const float bx = bias[col], by = bias[col + 1];
            float v00 = acc[mg][f][0] + bx, v01 = acc[mg][f][1] + by;
            float v10 = acc[mg][f][2] + bx, v11 = acc[mg][f][3] + by;
            if (RELU) {
                v00 = fmaxf(v00, 0.0f); v01 = fmaxf(v01, 0.0f);
                v10 = fmaxf(v10, 0.0f); v11 = fmaxf(v11, 0.0f);
            }
            if (mode == OUT_F32) {
                *reinterpret_cast<float2*>(C + (size_t)rr0 * Nn + col)       = make_float2(v00, v01);
                *reinterpret_cast<float2*>(C + (size_t)(rr0 + 8) * Nn + col) = make_float2(v10, v11);
            } else if (mode == OUT_PLANES) {
                uint32_t h0, l0, h1, l1;
                split2(v00, v01, h0, l0);
                split2(v10, v11, h1, l1);
                *reinterpret_cast<uint32_t*>(Phi + (size_t)rr0 * Nn + col)       = h0;
                *reinterpret_cast<uint32_t*>(Plo + (size_t)rr0 * Nn + col)       = l0;
                *reinterpret_cast<uint32_t*>(Phi + (size_t)(rr0 + 8) * Nn + col) = h1;
                *reinterpret_cast<uint32_t*>(Plo + (size_t)(rr0 + 8) * Nn + col) = l1;
            } else {   // OUT_HEADS
                const int hh = col >> 6, d = col & 63;
                const size_t base0 = (size_t)hh * (N_TOK * DKH) + (size_t)rr0 * DKH + d;
                const size_t base1 = base0 + 8 * DKH;
                uint32_t h0, l0, h1, l1;
                split2(v00 * oscale, v01 * oscale, h0, l0);
                split2(v10 * oscale, v11 * oscale, h1, l1);
                *reinterpret_cast<uint32_t*>(Phi + base0) = h0;
                *reinterpret_cast<uint32_t*>(Plo + base0) = l0;
                *reinterpret_cast<uint32_t*>(Phi + base1) = h1;
                *reinterpret_cast<uint32_t*>(Plo + base1) = l1;
            }
        }
    }
}

template <bool RELU>
__global__ __launch_bounds__(128) void gemm_mma(const __nv_bfloat16* __restrict__ Ahi,
                                                const __nv_bfloat16* __restrict__ Alo,
                                                const __nv_bfloat16* __restrict__ Bhi,
                                                const __nv_bfloat16* __restrict__ Blo,
                                                const float* __restrict__ bias,
                                                float* C,
                                                __nv_bfloat16* Phi, __nv_bfloat16* Plo,
                                                float oscale, int Nn, int K, int mode)
{
    gemm_mma_body<RELU>(Ahi, Alo, Bhi, Blo, bias, C, Phi, Plo, oscale, Nn, K, mode);
}

__global__ __launch_bounds__(128) void gemm_mma_qkv(const __nv_bfloat16* __restrict__ Ahi,
                                                    const __nv_bfloat16* __restrict__ Alo,
                                                    const float* __restrict__ bq,
                                                    const float* __restrict__ bk,
                                                    const float* __restrict__ bv,
                                                    __nv_bfloat16* qhi, __nv_bfloat16* qlo,
                                                    __nv_bfloat16* khi, __nv_bfloat16* klo,
                                                    float* Vo, float qscale)
{
    const __nv_bfloat16* whi; const __nv_bfloat16* wlo;
    const float* bias; float* C = nullptr;
    __nv_bfloat16 *phi = nullptr, *plo = nullptr;
    float sc = 1.0f; int mode;
    if (blockIdx.z == 0) {
        whi = g_w_hi + WOFF_Q; wlo = g_w_lo + WOFF_Q; bias = bq;
        phi = qhi; plo = qlo; sc = qscale; mode = OUT_HEADS;
    } else if (blockIdx.z == 1) {
        whi = g_w_hi + WOFF_K; wlo = g_w_lo + WOFF_K; bias = bk;
        phi = khi; plo = klo; mode = OUT_HEADS;
    } else {
        whi = g_w_hi + WOFF_V; wlo = g_w_lo + WOFF_V; bias = bv;
        C = Vo; mode = OUT_F32;
    }
    gemm_mma_body<false>(Ahi, Alo, whi, wlo, bias, C, phi, plo, sc, DM, DM, mode);
}

// ===================== tensor-core flash attention (unchanged R11) ========
__global__ __launch_bounds__(128) void attn_mma(
    const __nv_bfloat16* __restrict__ qhi, const __nv_bfloat16* __restrict__ qlo,
    const __nv_bfloat16* __restrict__ khi, const __nv_bfloat16* __restrict__ klo,
    const __nv_bfloat16* __restrict__ vt,
    const unsigned long long* __restrict__ adjb,
    __nv_bfloat16* __restrict__ cxhi, __nv_bfloat16* __restrict__ cxlo)
{
    __shared__ __align__(128) uint8_t s_khi[2 * 64 * SROW];
    __shared__ __align__(128) uint8_t s_klo[2 * 64 * SROW];
    __shared__ __align__(128) uint8_t s_vt [2 * 64 * SROW];

    const int tid = threadIdx.x, lid = tid & 31, wid = tid >> 5;
    const int h = blockIdx.y, q0 = blockIdx.x * 64;
    const int wm = wid * 16;
    const size_t hoff = (size_t)h * (N_TOK * DKH);

    const uint32_t skhi = smem_u32(s_khi), sklo = smem_u32(s_klo), svt = smem_u32(s_vt);

    uint32_t qa_h[4][4], qa_l[4][4];
    const int rr0 = q0 + wm + (lid >> 2);
    {
        const int cc = (lid & 3) * 2;
        #pragma unroll
        for (int ks = 0; ks < 4; ks++) {
            const size_t o0 = hoff + (size_t)rr0 * 64 + ks * 16 + cc;
            const size_t o1 = hoff + (size_t)(rr0 + 8) * 64 + ks * 16 + cc;
            qa_h[ks][0] = *reinterpret_cast<const uint32_t*>(qhi + o0);
            qa_h[ks][1] = *reinterpret_cast<const uint32_t*>(qhi + o1);
            qa_h[ks][2] = *reinterpret_cast<const uint32_t*>(qhi + o0 + 8);
            qa_h[ks][3] = *reinterpret_cast<const uint32_t*>(qhi + o1 + 8);
            qa_l[ks][0] = *reinterpret_cast<const uint32_t*>(qlo + o0);
            qa_l[ks][1] = *reinterpret_cast<const uint32_t*>(qlo + o1);
            qa_l[ks][2] = *reinterpret_cast<const uint32_t*>(qlo + o0 + 8);
            qa_l[ks][3] = *reinterpret_cast<const uint32_t*>(qlo + o1 + 8);
        }
    }

    const int b_row = ((lid >> 4) & 1) * 8 + (lid & 7);
    const int b_sel = (lid >> 3) & 1;

    float o_acc[8][4] = {};
    float lsum0 = 0.0f, lsum1 = 0.0f;

    {
        #pragma unroll
        for (int i = 0; i < 4; i++) {
            const int idx = tid + i * 128;
            const int row = idx >> 3, ch = (idx >> 2) & 1, u = idx & 3;
            const uint32_t doff = (uint32_t)((ch * 64 + row) * SROW + u * 16);
            cp16(skhi + doff, khi + hoff + (size_t)row * 64 + ch * 32 + u * 8);
            cp16(sklo + doff, klo + hoff + (size_t)row * 64 + ch * 32 + u * 8);
            cp16(svt  + doff, vt  + hoff + (size_t)row * N_TOK + ch * 32 + u * 8);
        }
        asm volatile("cp.async.commit_group;");
    }

    for (int kb = 0; kb < N_TOK / 64; kb++) {
        asm volatile("cp.async.wait_group 0;" ::: "memory");
        __syncthreads();

        float sc[8][4] = {};
        #pragma unroll
        for (int ks = 0; ks < 4; ks++) {
            const uint32_t base = (uint32_t)(((ks >> 1) * 64 + b_row) * SROW
                                             + ((ks & 1) * 2 + b_sel) * 16);
            #pragma unroll
            for (int t = 0; t < 4; t++) {
                uint32_t bh[4], bl[4];
                ldm_x4(bh, skhi + base + t * 16 * SROW);
                ldm_x4(bl, sklo + base + t * 16 * SROW);
                #pragma unroll
                for (int t2 = 0; t2 < 2; t2++) {
                    float* d = sc[t * 2 + t2];
                    mma_bf16(d, qa_h[ks], &bh[t2 * 2]);
                    mma_bf16(d, qa_h[ks], &bl[t2 * 2]);
                    mma_bf16(d, qa_l[ks], &bh[t2 * 2]);
                }
            }
        }

        const unsigned long long w0 = adjb[(size_t)rr0 * 64 + kb];
        const unsigned long long w1 = adjb[(size_t)(rr0 + 8) * 64 + kb];
        uint32_t pa[4][4];
        #pragma unroll
        for (int f = 0; f < 8; f++) {
            const int cb = f * 8 + (lid & 3) * 2;
            const float s0 = ((w0 >> cb) & 1)       ? sc[f][0] : -102.0f;
            const float s1 = ((w0 >> (cb + 1)) & 1) ? sc[f][1] : -102.0f;
            const float s2 = ((w1 >> cb) & 1)       ? sc[f][2] : -102.0f;
            const float s3 = ((w1 >> (cb + 1)) & 1) ? sc[f][3] : -102.0f;
            const float p0 = fexp2b(s0), p1 = fexp2b(s1);
            const float p2 = fexp2b(s2), p3 = fexp2b(s3);
            lsum0 += p0 + p1; lsum1 += p2 + p3;
            __nv_bfloat162 x01 = __floats2bfloat162_rn(p0, p1);
            __nv_bfloat162 x23 = __floats2bfloat162_rn(p2, p3);
            const int j = f >> 1, oo = (f & 1) * 2;
            pa[j][oo]     = *reinterpret_cast<uint32_t*>(&x01);
            pa[j][oo + 1] = *reinterpret_cast<uint32_t*>(&x23);
        }

        #pragma unroll
        for (int ks = 0; ks < 4; ks++) {
            const uint32_t base = (uint32_t)(((ks >> 1) * 64 + b_row) * SROW
                                             + ((ks & 1) * 2 + b_sel) * 16);
            #pragma unroll
            for (int t = 0; t < 4; t++) {
                uint32_t bv[4];
                ldm_x4(bv, svt + base + t * 16 * SROW);
                mma_bf16(o_acc[t * 2],     pa[ks], &bv[0]);
                mma_bf16(o_acc[t * 2 + 1], pa[ks], &bv[2]);
            }
        }

        __syncthreads();
        if (kb < N_TOK / 64 - 1) {
            const int k0 = (kb + 1) * 64;
            #pragma unroll
            for (int i = 0; i < 4; i++) {
                const int idx = tid + i * 128;
                const int row = idx >> 3, ch = (idx >> 2) & 1, u = idx & 3;
                const uint32_t doff = (uint32_t)((ch * 64 + row) * SROW + u * 16);
                cp16(skhi + doff, khi + hoff + (size_t)(k0 + row) * 64 + ch * 32 + u * 8);
                cp16(sklo + doff, klo + hoff + (size_t)(k0 + row) * 64 + ch * 32 + u * 8);
                cp16(svt  + doff, vt  + hoff + (size_t)row * N_TOK + k0 + ch * 32 + u * 8);
            }
            asm volatile("cp.async.commit_group;");
        }
    }

    lsum0 += __shfl_xor_sync(0xffffffffu, lsum0, 1);
    lsum0 += __shfl_xor_sync(0xffffffffu, lsum0, 2);
    lsum1 += __shfl_xor_sync(0xffffffffu, lsum1, 1);
    lsum1 += __shfl_xor_sync(0xffffffffu, lsum1, 2);
    const float inv0 = 1.0f / lsum0, inv1 = 1.0f / lsum1;
    const int col0 = h * DKH + (lid & 3) * 2;
    #pragma unroll
    for (int f = 0; f < 8; f++) {
        uint32_t h0, l0, h1, l1;
        split2(o_acc[f][0] * inv0, o_acc[f][1] * inv0, h0, l0);
        split2(o_acc[f][2] * inv1, o_acc[f][3] * inv1, h1, l1);
        const size_t a0 = (size_t)rr0 * DM + col0 + f * 8;
        const size_t a1 = (size_t)(rr0 + 8) * DM + col0 + f * 8;
        *reinterpret_cast<uint32_t*>(cxhi + a0) = h0;
        *reinterpret_cast<uint32_t*>(cxlo + a0) = l0;
        *reinterpret_cast<uint32_t*>(cxhi + a1) = h1;
        *reinterpret_cast<uint32_t*>(cxlo + a1) = l1;
    }
}

// ---------------------------------------------------------------------------
// out = LayerNorm(x + r) * g + b; optionally also write hi/lo planes
// ---------------------------------------------------------------------------
template <bool PLANES>
__global__ __launch_bounds__(128) void ln_kernel(const float* __restrict__ x,
                                                 const float* __restrict__ r,
                                                 const float* __restrict__ g,
                                                 const float* __restrict__ b,
                                                 float* __restrict__ out,
                                                 __nv_bfloat16* __restrict__ phi,
                                                 __nv_bfloat16* __restrict__ plo)
{
    __shared__ float ws[4], ws2[4];
    const int row = blockIdx.x;
    const int tid = threadIdx.x;
    const int col = tid * 4;

    float4 xv = *reinterpret_cast<const float4*>(&x[(size_t)row * DM + col]);
    float4 rv = *reinterpret_cast<const float4*>(&r[(size_t)row * DM + col]);
    float v[4] = {xv.x + rv.x, xv.y + rv.y, xv.z + rv.z, xv.w + rv.w};

    float s = 0.0f, s2 = 0.0f;
    #pragma unroll
    for (int c = 0; c < 4; c++) { s += v[c]; s2 = fmaf(v[c], v[c], s2); }
    #pragma unroll
    for (int off = 16; off >= 1; off >>= 1) {
        s  += __shfl_xor_sync(0xffffffffu, s,  off);
        s2 += __shfl_xor_sync(0xffffffffu, s2, off);
    }
    const int wid = tid >> 5;
    if ((tid & 31) == 0) { ws[wid] = s; ws2[wid] = s2; }
    __syncthreads();
    const float S  = ws[0] + ws[1] + ws[2] + ws[3];
    const float S2 = ws2[0] + ws2[1] + ws2[2] + ws2[3];
    const float mean = S * (1.0f / DM);
    const float var  = S2 * (1.0f / DM) - mean * mean;
    const float rstd = rsqrtf(var + 1e-5f);

    float4 gv = *reinterpret_cast<const float4*>(&g[col]);
    float4 bv = *reinterpret_cast<const float4*>(&b[col]);
    float gr[4] = {gv.x, gv.y, gv.z, gv.w};
    float br[4] = {bv.x, bv.y, bv.z, bv.w};
    float4 ov; float* op = &ov.x;
    #pragma unroll
    for (int c = 0; c < 4; c++)
        op[c] = (v[c] - mean) * rstd * gr[c] + br[c];
    *reinterpret_cast<float4*>(&out[(size_t)row * DM + col]) = ov;
    if (PLANES) {
        uint32_t h0, l0, h1, l1;
        split2(ov.x, ov.y, h0, l0);
        split2(ov.z, ov.w, h1, l1);
        *reinterpret_cast<uint32_t*>(phi + (size_t)row * DM + col)     = h0;
        *reinterpret_cast<uint32_t*>(plo + (size_t)row * DM + col)     = l0;
        *reinterpret_cast<uint32_t*>(phi + (size_t)row * DM + col + 2) = h1;
        *reinterpret_cast<uint32_t*>(plo + (size_t)row * DM + col + 2) = l1;
    }
}

// ---------------------------------------------------------------------------
extern "C" void kernel_launch(void* const* d_in, const int* in_sizes, int n_in,
                              void* d_out, int out_size)
{
    const float* h    = (const float*)d_in[0];
    const int*   adj  = (const int*)d_in[1];
    const float* Wq   = (const float*)d_in[2];
    const float* bq   = (const float*)d_in[3];
    const float* Wk   = (const float*)d_in[4];
    const float* bk   = (const float*)d_in[5];
    const float* Wv   = (const float*)d_in[6];
    const float* bv   = (const float*)d_in[7];
    const float* Wo   = (const float*)d_in[8];
    const float* bo   = (const float*)d_in[9];
    const float* W1   = (const float*)d_in[10];
    const float* b1   = (const float*)d_in[11];
    const float* W2   = (const float*)d_in[12];
    const float* b2   = (const float*)d_in[13];
    const float* ln1g = (const float*)d_in[14];
    const float* ln1b = (const float*)d_in[15];
    const float* ln2g = (const float*)d_in[16];
    const float* ln2b = (const float*)d_in[17];
    float* out = (float*)d_out;

    float *Vd, *tmp, *h1;
    cudaGetSymbolAddress((void**)&Vd,  g_V);
    cudaGetSymbolAddress((void**)&tmp, g_tmp);
    cudaGetSymbolAddress((void**)&h1,  g_h1);

    __nv_bfloat16 *hb_hi, *hb_lo, *cx_hi, *cx_lo, *h1_hi, *h1_lo, *ff_hi, *ff_lo, *w_hi, *w_lo;
    __nv_bfloat16 *qs_hi, *qs_lo, *ks_hi, *ks_lo, *vtp;
    unsigned long long* adjb;
    cudaGetSymbolAddress((void**)&hb_hi, g_hb_hi);
    cudaGetSymbolAddress((void**)&hb_lo, g_hb_lo);
    cudaGetSymbolAddress((void**)&cx_hi, g_cx_hi);
    cudaGetSymbolAddress((void**)&cx_lo, g_cx_lo);
    cudaGetSymbolAddress((void**)&h1_hi, g_h1_hi);
    cudaGetSymbolAddress((void**)&h1_lo, g_h1_lo);
    cudaGetSymbolAddress((void**)&ff_hi, g_ff_hi);
    cudaGetSymbolAddress((void**)&ff_lo, g_ff_lo);
    cudaGetSymbolAddress((void**)&w_hi,  g_w_hi);
    cudaGetSymbolAddress((void**)&w_lo,  g_w_lo);
    cudaGetSymbolAddress((void**)&qs_hi, g_qs_hi);
    cudaGetSymbolAddress((void**)&qs_lo, g_qs_lo);
    cudaGetSymbolAddress((void**)&ks_hi, g_ks_hi);
    cudaGetSymbolAddress((void**)&ks_lo, g_ks_lo);
    cudaGetSymbolAddress((void**)&vtp,   g_vt);
    cudaGetSymbolAddress((void**)&adjb,  g_adjb);

    // opt-in to 60KB dynamic smem for the GEMM kernels (idempotent)
    cudaFuncSetAttribute(gemm_mma_qkv,
                         cudaFuncAttributeMaxDynamicSharedMemorySize, GEMM_SMEM);
    cudaFuncSetAttribute(gemm_mma<false>,
                         cudaFuncAttributeMaxDynamicSharedMemorySize, GEMM_SMEM);
    cudaFuncSetAttribute(gemm_mma<true>,
                         cudaFuncAttributeMaxDynamicSharedMemorySize, GEMM_SMEM);

    const int ACT = N_TOK * DM;
    const float QSCALE = 1.4426950408889634f / 8.0f;   // log2(e)/sqrt(d_k)

    const dim3 blk(128);
    const dim3 gQKV(DM / 64, N_TOK / 128, 3);
    const dim3 gP(DM / 64, N_TOK / 128);
    const dim3 gF1(DFF / 64, N_TOK / 128);

    // launches ordered so attn_mma is the 6th launch (ncu -s 5 profiles it)
    pack_adj<<<(N_TOK * 64) / 256, 256>>>(adj, adjb);                       // 1
    convert_split<<<1024, 256>>>(h, hb_hi, hb_lo, ACT);                     // 2
    convert_w<<<2048, 256>>>(Wq, Wk, Wv, Wo, W1, W2, w_hi, w_lo);           // 3
    gemm_mma_qkv<<<gQKV, blk, GEMM_SMEM>>>(hb_hi, hb_lo, bq, bk, bv,        // 4
                                           qs_hi, qs_lo, ks_hi, ks_lo, Vd, QSCALE);
    convert_v_t<<<dim3(N_TOK / 64, NH), 256>>>(Vd, vtp);                    // 5
    attn_mma<<<dim3(N_TOK / 64, NH), blk>>>(qs_hi, qs_lo, ks_hi, ks_lo,     // 6
                                            vtp, adjb, cx_hi, cx_lo);
    gemm_mma<false><<<gP, blk, GEMM_SMEM>>>(cx_hi, cx_lo, w_hi + WOFF_O, w_lo + WOFF_O,
                                            bo, tmp, nullptr, nullptr, 1.0f, DM, DM, OUT_F32);
    ln_kernel<true><<<N_TOK, 128>>>(h, tmp, ln1g, ln1b, h1, h1_hi, h1_lo);
    gemm_mma<true><<<gF1, blk, GEMM_SMEM>>>(h1_hi, h1_lo, w_hi + WOFF_1, w_lo + WOFF_1,
                                            b1, nullptr, ff_hi, ff_lo, 1.0f, DFF, DM, OUT_PLANES);
    gemm_mma<false><<<gP, blk, GEMM_SMEM>>>(ff_hi, ff_lo, w_hi + WOFF_2, w_lo + WOFF_2,
                                            b2, tmp, nullptr, nullptr, 1.0f, DM, DFF, OUT_F32);
    ln_kernel<false><<<N_TOK, 128>>>(h1, tmp, ln2g, ln2b, out, nullptr, nullptr);
}

// round 13
// speedup vs baseline: 1.0361x; 1.0157x over previous
#include <cuda_runtime.h>
#include <cuda_bf16.h>
#include <cstdint>

#define N_TOK 4096
#define DM    512
#define NH    8
#define DKH   64
#define DFF   2048

// ---------------- scratch (device globals; no runtime allocation) ----------
__device__ float g_V[N_TOK * DM];
__device__ float g_tmp[N_TOK * DM];
__device__ float g_h1[N_TOK * DM];

// bf16 hi/lo planes
__device__ __nv_bfloat16 g_hb_hi[N_TOK * DM],  g_hb_lo[N_TOK * DM];
__device__ __nv_bfloat16 g_cx_hi[N_TOK * DM],  g_cx_lo[N_TOK * DM];
__device__ __nv_bfloat16 g_h1_hi[N_TOK * DM],  g_h1_lo[N_TOK * DM];
__device__ __nv_bfloat16 g_ff_hi[(size_t)N_TOK * DFF], g_ff_lo[(size_t)N_TOK * DFF];
#define WOFF_Q  0
#define WOFF_K  (512 * 512)
#define WOFF_V  (2 * 512 * 512)
#define WOFF_O  (3 * 512 * 512)
#define WOFF_1  (4 * 512 * 512)
#define WOFF_2  (4 * 512 * 512 + 2048 * 512)
#define WTOT    (4 * 512 * 512 + 2 * 2048 * 512)
__device__ __nv_bfloat16 g_w_hi[WTOT], g_w_lo[WTOT];

// attention: per-head bf16 planes [h][tok][64], V transposed [h][d][tok]
__device__ __nv_bfloat16 g_qs_hi[NH * N_TOK * DKH], g_qs_lo[NH * N_TOK * DKH];
__device__ __nv_bfloat16 g_ks_hi[NH * N_TOK * DKH], g_ks_lo[NH * N_TOK * DKH];
__device__ __nv_bfloat16 g_vt[NH * DKH * N_TOK];
__device__ unsigned long long g_adjb[N_TOK * (N_TOK / 64)];

// epilogue output modes
#define OUT_F32    0
#define OUT_PLANES 1
#define OUT_HEADS  2

// ===================== low-level helpers ==================================
__device__ __forceinline__ uint32_t smem_u32(const void* p) {
    uint32_t a;
    asm("{ .reg .u64 t; cvta.to.shared.u64 t, %1; cvt.u32.u64 %0, t; }"
        : "=r"(a) : "l"(p));
    return a;
}
__device__ __forceinline__ void cp16(uint32_t dst, const void* src) {
    asm volatile("cp.async.cg.shared.global [%0], [%1], 16;" :: "r"(dst), "l"(src));
}
__device__ __forceinline__ void ldm_x4(uint32_t* r, uint32_t addr) {
    asm volatile("ldmatrix.sync.aligned.m8n8.x4.shared.b16 {%0,%1,%2,%3}, [%4];"
                 : "=r"(r[0]), "=r"(r[1]), "=r"(r[2]), "=r"(r[3]) : "r"(addr));
}
__device__ __forceinline__ void mma_bf16(float* d, const uint32_t* a, const uint32_t* b) {
    asm volatile("mma.sync.aligned.m16n8k16.row.col.f32.bf16.bf16.f32 "
                 "{%0,%1,%2,%3},{%4,%5,%6,%7},{%8,%9},{%0,%1,%2,%3};"
                 : "+f"(d[0]), "+f"(d[1]), "+f"(d[2]), "+f"(d[3])
                 : "r"(a[0]), "r"(a[1]), "r"(a[2]), "r"(a[3]),
                   "r"(b[0]), "r"(b[1]));
}
__device__ __forceinline__ float fexp2b(float s) {
    const float C1 = 12582904.0f;                 // 1.5*2^23 - 8
    float t  = s + C1;
    float v  = t - C1;
    float zf = s - v;
    int   zi = __float_as_int(t) - 0x4B400000;
    float p = fmaf(zf, 0.00961813f, 0.05550411f);
    p = fmaf(zf, p, 0.24022651f);
    p = fmaf(zf, p, 0.69314718f);
    p = fmaf(zf, p, 1.0f);
    return __int_as_float(__float_as_int(p) + (zi << 23));
}
__device__ __forceinline__ void split2(float x, float y, uint32_t& hi, uint32_t& lo) {
    __nv_bfloat162 h = __floats2bfloat162_rn(x, y);
    float hx = __bfloat162float(h.x), hy = __bfloat162float(h.y);
    __nv_bfloat162 l = __floats2bfloat162_rn(x - hx, y - hy);
    hi = *reinterpret_cast<uint32_t*>(&h);
    lo = *reinterpret_cast<uint32_t*>(&l);
}

// ===================== element-wise prep kernels ==========================
__global__ __launch_bounds__(256) void convert_split(const float* __restrict__ in,
                                                     __nv_bfloat16* __restrict__ hi,
                                                     __nv_bfloat16* __restrict__ lo,
                                                     int n)
{
    for (int i = (blockIdx.x * 256 + threadIdx.x) * 4; i < n; i += gridDim.x * 1024) {
        float4 v = *reinterpret_cast<const float4*>(in + i);
        uint32_t h0, l0, h1, l1;
        split2(v.x, v.y, h0, l0);
        split2(v.z, v.w, h1, l1);
        *reinterpret_cast<uint32_t*>(hi + i)     = h0;
        *reinterpret_cast<uint32_t*>(hi + i + 2) = h1;
        *reinterpret_cast<uint32_t*>(lo + i)     = l0;
        *reinterpret_cast<uint32_t*>(lo + i + 2) = l1;
    }
}

__global__ __launch_bounds__(256) void convert_w(const float* __restrict__ Wq,
                                                 const float* __restrict__ Wk,
                                                 const float* __restrict__ Wv,
                                                 const float* __restrict__ Wo,
                                                 const float* __restrict__ W1,
                                                 const float* __restrict__ W2,
                                                 __nv_bfloat16* __restrict__ hi,
                                                 __nv_bfloat16* __restrict__ lo)
{
    const int WSQ = 512 * 512, WFF = 2048 * 512;
    for (int i = (blockIdx.x * 256 + threadIdx.x) * 4; i < WTOT; i += gridDim.x * 1024) {
        const float* src; int off;
        if (i < 4 * WSQ)            { int r = i / WSQ; off = i - r * WSQ;
                                      src = (r == 0) ? Wq : (r == 1) ? Wk : (r == 2) ? Wv : Wo; }
        else if (i < 4 * WSQ + WFF) { src = W1; off = i - 4 * WSQ; }
        else                        { src = W2; off = i - 4 * WSQ - WFF; }
        float4 v = *reinterpret_cast<const float4*>(src + off);
        uint32_t h0, l0, h1, l1;
        split2(v.x, v.y, h0, l0);
        split2(v.z, v.w, h1, l1);
        *reinterpret_cast<uint32_t*>(hi + i)     = h0;
        *reinterpret_cast<uint32_t*>(hi + i + 2) = h1;
        *reinterpret_cast<uint32_t*>(lo + i)     = l0;
        *reinterpret_cast<uint32_t*>(lo + i + 2) = l1;
    }
}

__global__ __launch_bounds__(256) void convert_v_t(const float* __restrict__ V,
                                                   __nv_bfloat16* __restrict__ vt)
{
    __shared__ float sm[64][65];
    const int h = blockIdx.y, t0 = blockIdx.x * 64;
    const int tid = threadIdx.x;
    for (int i = tid; i < 1024; i += 256) {
        int r = i >> 4, c4 = (i & 15) * 4;
        float4 v = *reinterpret_cast<const float4*>(&V[(size_t)(t0 + r) * DM + h * DKH + c4]);
        sm[c4][r] = v.x; sm[c4 + 1][r] = v.y; sm[c4 + 2][r] = v.z; sm[c4 + 3][r] = v.w;
    }
    __syncthreads();
    for (int i = tid; i < 2048; i += 256) {
        int d = i >> 5, pr = i & 31;
        __nv_bfloat162 b = __floats2bfloat162_rn(sm[d][2 * pr], sm[d][2 * pr + 1]);
        *reinterpret_cast<__nv_bfloat162*>(
            vt + (size_t)h * (DKH * N_TOK) + (size_t)d * N_TOK + t0 + 2 * pr) = b;
    }
}

__global__ __launch_bounds__(256) void pack_adj(const int* __restrict__ adj,
                                                unsigned long long* __restrict__ bits)
{
    int gid = blockIdx.x * 256 + threadIdx.x;
    int r = gid >> 6, w = gid & 63;
    const int4* p = reinterpret_cast<const int4*>(adj + (size_t)r * N_TOK + w * 64);
    unsigned long long b = 0;
    #pragma unroll
    for (int i = 0; i < 16; i++) {
        int4 a = p[i];
        if (a.x) b |= 1ull << (i * 4 + 0);
        if (a.y) b |= 1ull << (i * 4 + 1);
        if (a.z) b |= 1ull << (i * 4 + 2);
        if (a.w) b |= 1ull << (i * 4 + 3);
    }
    if ((r >> 6) == w) b |= 1ull << (r & 63);
    bits[gid] = b;
}

// ===================== 128x64-tile pipelined split-bf16 GEMM ==============
// CTA = 128m x 64n, 4 warps, warp = 32m x 64n. k-chunk 32, 2-stage pipeline.
// MMA issue is pass-structured: 16 independent accumulators between reuses.
#define SROW 80
#define GS_AH 0
#define GS_AL 10240
#define GS_BH 20480
#define GS_BL 25600
#define GS_STAGE 30720
#define GEMM_SMEM (2 * GS_STAGE)

extern __shared__ __align__(128) uint8_t g_dyn[];

__device__ __forceinline__ void gemm_load_chunk(
    uint32_t sbase,
    const __nv_bfloat16* gA_hi, const __nv_bfloat16* gA_lo,
    const __nv_bfloat16* gB_hi, const __nv_bfloat16* gB_lo,
    int K, int c, int tid)
{
    const int u  = tid & 3;
    const int gk = c * 32 + u * 8;
    #pragma unroll
    for (int i = 0; i < 4; i++) {      // A: 128 rows
        const int row = (tid >> 2) + i * 32;
        const uint32_t doff = (uint32_t)(row * SROW + u * 16);
        const size_t go = (size_t)row * K + gk;
        cp16(sbase + GS_AH + doff, gA_hi + go);
        cp16(sbase + GS_AL + doff, gA_lo + go);
    }
    #pragma unroll
    for (int i = 0; i < 2; i++) {      // B: 64 rows
        const int row = (tid >> 2) + i * 32;
        const uint32_t doff = (uint32_t)(row * SROW + u * 16);
        const size_t go = (size_t)row * K + gk;
        cp16(sbase + GS_BH + doff, gB_hi + go);
        cp16(sbase + GS_BL + doff, gB_lo + go);
    }
    asm volatile("cp.async.commit_group;");
}

template <bool RELU>
__device__ __forceinline__ void gemm_mma_body(const __nv_bfloat16* __restrict__ Ahi,
                                              const __nv_bfloat16* __restrict__ Alo,
                                              const __nv_bfloat16* __restrict__ Bhi,
                                              const __nv_bfloat16* __restrict__ Blo,
                                              const float* __restrict__ bias,
                                              float* __restrict__ C,
                                              __nv_bfloat16* __restrict__ Phi,
                                              __nv_bfloat16* __restrict__ Plo,
                                              float oscale,
                                              int Nn, int K, int mode)
{
    const int tid = threadIdx.x, lid = tid & 31, wid = tid >> 5;
    const int wm  = wid * 32;
    const int m0  = blockIdx.y * 128, n0 = blockIdx.x * 64;

    const uint32_t sb0 = smem_u32(g_dyn);
    const uint32_t sb[2] = {sb0, sb0 + GS_STAGE};

    const __nv_bfloat16* gA_hi = Ahi + (size_t)m0 * K;
    const __nv_bfloat16* gA_lo = Alo + (size_t)m0 * K;
    const __nv_bfloat16* gB_hi = Bhi + (size_t)n0 * K;
    const __nv_bfloat16* gB_lo = Blo + (size_t)n0 * K;

    const int a_row = lid & 15;
    const int a_sel = lid >> 4;
    const int b_row = ((lid >> 4) & 1) * 8 + (lid & 7);
    const int b_sel = (lid >> 3) & 1;

    float acc[2][8][4] = {};

    const int nch = K >> 5;
    gemm_load_chunk(sb[0], gA_hi, gA_lo, gB_hi, gB_lo, K, 0, tid);
    if (nch > 1)
        gemm_load_chunk(sb[1], gA_hi, gA_lo, gB_hi, gB_lo, K, 1, tid);

    for (int c = 0; c < nch; c++) {
        if (c == nch - 1) asm volatile("cp.async.wait_group 0;" ::: "memory");
        else              asm volatile("cp.async.wait_group 1;" ::: "memory");
        __syncthreads();

        const uint32_t st = sb[c & 1];
        #pragma unroll
        for (int ks = 0; ks < 2; ks++) {
            uint32_t ah[2][4], al[2][4];
            #pragma unroll
            for (int mg = 0; mg < 2; mg++) {
                const uint32_t aoff = (uint32_t)((wm + mg * 16 + a_row) * SROW
                                                 + (ks * 2 + a_sel) * 16);
                ldm_x4(ah[mg], st + GS_AH + aoff);
                ldm_x4(al[mg], st + GS_AL + aoff);
            }
            uint32_t bh[4][4], bl[4][4];
            #pragma unroll
            for (int t = 0; t < 4; t++) {
                const uint32_t boff = (uint32_t)((t * 16 + b_row) * SROW
                                                 + (ks * 2 + b_sel) * 16);
                ldm_x4(bh[t], st + GS_BH + boff);
                ldm_x4(bl[t], st + GS_BL + boff);
            }
            // pass 1: ah * bh  (16 independent accumulators)
            #pragma unroll
            for (int t = 0; t < 4; t++)
                #pragma unroll
                for (int mg = 0; mg < 2; mg++)
                    #pragma unroll
                    for (int t2 = 0; t2 < 2; t2++)
                        mma_bf16(acc[mg][t * 2 + t2], ah[mg], &bh[t][t2 * 2]);
            // pass 2: ah * bl
            #pragma unroll
            for (int t = 0; t < 4; t++)
                #pragma unroll
                for (int mg = 0; mg < 2; mg++)
                    #pragma unroll
                    for (int t2 = 0; t2 < 2; t2++)
                        mma_bf16(acc[mg][t * 2 + t2], ah[mg], &bl[t][t2 * 2]);
            // pass 3: al * bh
            #pragma unroll
            for (int t = 0; t < 4; t++)
                #pragma unroll
                for (int mg = 0; mg < 2; mg++)
                    #pragma unroll
                    for (int t2 = 0; t2 < 2; t2++)
                        mma_bf16(acc[mg][t * 2 + t2], al[mg], &bh[t][t2 * 2]);
        }
        __syncthreads();
        if (c + 2 < nch)
            gemm_load_chunk(sb[c & 1], gA_hi, gA_lo, gB_hi, gB_lo, K, c + 2, tid);
    }

    // epilogue
    const int cbase = n0 + (lid & 3) * 2;
    #pragma unroll
    for (int mg = 0; mg < 2; mg++) {
        const int rr0 = m0 + wm + mg * 16 + (lid >> 2);
        #pragma unroll
        for (int f = 0; f < 8; f++) {
            const int col = cbase + f * 8;
            const float bx = bias[col], by = bias[col + 1];
            float v00 = acc[mg][f][0] + bx, v01 = acc[mg][f][1] + by;
            float v10 = acc[mg][f][2] + bx, v11 = acc[mg][f][3] + by;
            if (RELU) {
                v00 = fmaxf(v00, 0.0f); v01 = fmaxf(v01, 0.0f);
                v10 = fmaxf(v10, 0.0f); v11 = fmaxf(v11, 0.0f);
            }
            if (mode == OUT_F32) {
                *reinterpret_cast<float2*>(C + (size_t)rr0 * Nn + col)       = make_float2(v00, v01);
                *reinterpret_cast<float2*>(C + (size_t)(rr0 + 8) * Nn + col) = make_float2(v10, v11);
            } else if (mode == OUT_PLANES) {
                uint32_t h0, l0, h1, l1;
                split2(v00, v01, h0, l0);
                split2(v10, v11, h1, l1);
                *reinterpret_cast<uint32_t*>(Phi + (size_t)rr0 * Nn + col)       = h0;
                *reinterpret_cast<uint32_t*>(Plo + (size_t)rr0 * Nn + col)       = l0;
                *reinterpret_cast<uint32_t*>(Phi + (size_t)(rr0 + 8) * Nn + col) = h1;
                *reinterpret_cast<uint32_t*>(Plo + (size_t)(rr0 + 8) * Nn + col) = l1;
            } else {   // OUT_HEADS
                const int hh = col >> 6, d = col & 63;
                const size_t base0 = (size_t)hh * (N_TOK * DKH) + (size_t)rr0 * DKH + d;
                const size_t base1 = base0 + 8 * DKH;
                uint32_t h0, l0, h1, l1;
                split2(v00 * oscale, v01 * oscale, h0, l0);
                split2(v10 * oscale, v11 * oscale, h1, l1);
                *reinterpret_cast<uint32_t*>(Phi + base0) = h0;
                *reinterpret_cast<uint32_t*>(Plo + base0) = l0;
                *reinterpret_cast<uint32_t*>(Phi + base1) = h1;
                *reinterpret_cast<uint32_t*>(Plo + base1) = l1;
            }
        }
    }
}

template <bool RELU>
__global__ __launch_bounds__(128) void gemm_mma(const __nv_bfloat16* __restrict__ Ahi,
                                                const __nv_bfloat16* __restrict__ Alo,
                                                const __nv_bfloat16* __restrict__ Bhi,
                                                const __nv_bfloat16* __restrict__ Blo,
                                                const float* __restrict__ bias,
                                                float* C,
                                                __nv_bfloat16* Phi, __nv_bfloat16* Plo,
                                                float oscale, int Nn, int K, int mode)
{
    gemm_mma_body<RELU>(Ahi, Alo, Bhi, Blo, bias, C, Phi, Plo, oscale, Nn, K, mode);
}

__global__ __launch_bounds__(128) void gemm_mma_qkv(const __nv_bfloat16* __restrict__ Ahi,
                                                    const __nv_bfloat16* __restrict__ Alo,
                                                    const float* __restrict__ bq,
                                                    const float* __restrict__ bk,
                                                    const float* __restrict__ bv,
                                                    __nv_bfloat16* qhi, __nv_bfloat16* qlo,
                                                    __nv_bfloat16* khi, __nv_bfloat16* klo,
                                                    float* Vo, float qscale)
{
    const __nv_bfloat16* whi; const __nv_bfloat16* wlo;
    const float* bias; float* C = nullptr;
    __nv_bfloat16 *phi = nullptr, *plo = nullptr;
    float sc = 1.0f; int mode;
    if (blockIdx.z == 0) {
        whi = g_w_hi + WOFF_Q; wlo = g_w_lo + WOFF_Q; bias = bq;
        phi = qhi; plo = qlo; sc = qscale; mode = OUT_HEADS;
    } else if (blockIdx.z == 1) {
        whi = g_w_hi + WOFF_K; wlo = g_w_lo + WOFF_K; bias = bk;
        phi = khi; plo = klo; mode = OUT_HEADS;
    } else {
        whi = g_w_hi + WOFF_V; wlo = g_w_lo + WOFF_V; bias = bv;
        C = Vo; mode = OUT_F32;
    }
    gemm_mma_body<false>(Ahi, Alo, whi, wlo, bias, C, phi, plo, sc, DM, DM, mode);
}

// ===================== tensor-core flash attention ========================
// q-tile 128, 256 threads (8 warps x 16 q-rows). K/V smem shared by 2x math.
__global__ __launch_bounds__(256, 1) void attn_mma(
    const __nv_bfloat16* __restrict__ qhi, const __nv_bfloat16* __restrict__ qlo,
    const __nv_bfloat16* __restrict__ khi, const __nv_bfloat16* __restrict__ klo,
    const __nv_bfloat16* __restrict__ vt,
    const unsigned long long* __restrict__ adjb,
    __nv_bfloat16* __restrict__ cxhi, __nv_bfloat16* __restrict__ cxlo)
{
    __shared__ __align__(128) uint8_t s_khi[2 * 64 * SROW];
    __shared__ __align__(128) uint8_t s_klo[2 * 64 * SROW];
    __shared__ __align__(128) uint8_t s_vt [2 * 64 * SROW];

    const int tid = threadIdx.x, lid = tid & 31, wid = tid >> 5;
    const int h = blockIdx.y, q0 = blockIdx.x * 128;
    const int wm = wid * 16;
    const size_t hoff = (size_t)h * (N_TOK * DKH);

    const uint32_t skhi = smem_u32(s_khi), sklo = smem_u32(s_klo), svt = smem_u32(s_vt);

    uint32_t qa_h[4][4], qa_l[4][4];
    const int rr0 = q0 + wm + (lid >> 2);
    {
        const int cc = (lid & 3) * 2;
        #pragma unroll
        for (int ks = 0; ks < 4; ks++) {
            const size_t o0 = hoff + (size_t)rr0 * 64 + ks * 16 + cc;
            const size_t o1 = hoff + (size_t)(rr0 + 8) * 64 + ks * 16 + cc;
            qa_h[ks][0] = *reinterpret_cast<const uint32_t*>(qhi + o0);
            qa_h[ks][1] = *reinterpret_cast<const uint32_t*>(qhi + o1);
            qa_h[ks][2] = *reinterpret_cast<const uint32_t*>(qhi + o0 + 8);
            qa_h[ks][3] = *reinterpret_cast<const uint32_t*>(qhi + o1 + 8);
            qa_l[ks][0] = *reinterpret_cast<const uint32_t*>(qlo + o0);
            qa_l[ks][1] = *reinterpret_cast<const uint32_t*>(qlo + o1);
            qa_l[ks][2] = *reinterpret_cast<const uint32_t*>(qlo + o0 + 8);
            qa_l[ks][3] = *reinterpret_cast<const uint32_t*>(qlo + o1 + 8);
        }
    }

    const int b_row = ((lid >> 4) & 1) * 8 + (lid & 7);
    const int b_sel = (lid >> 3) & 1;

    float o_acc[8][4] = {};
    float lsum0 = 0.0f, lsum1 = 0.0f;

    {
        #pragma unroll
        for (int i = 0; i < 2; i++) {
            const int idx = tid + i * 256;
            const int row = idx >> 3, ch = (idx >> 2) & 1, u = idx & 3;
            const uint32_t doff = (uint32_t)((ch * 64 + row) * SROW + u * 16);
            cp16(skhi + doff, khi + hoff + (size_t)row * 64 + ch * 32 + u * 8);
            cp16(sklo + doff, klo + hoff + (size_t)row * 64 + ch * 32 + u * 8);
            cp16(svt  + doff, vt  + hoff + (size_t)row * N_TOK + ch * 32 + u * 8);
        }
        asm volatile("cp.async.commit_group;");
    }

    for (int kb = 0; kb < N_TOK / 64; kb++) {
        asm volatile("cp.async.wait_group 0;" ::: "memory");
        __syncthreads();

        float sc[8][4] = {};
        #pragma unroll
        for (int ks = 0; ks < 4; ks++) {
            const uint32_t base = (uint32_t)(((ks >> 1) * 64 + b_row) * SROW
                                             + ((ks & 1) * 2 + b_sel) * 16);
            #pragma unroll
            for (int t = 0; t < 4; t++) {
                uint32_t bh[4], bl[4];
                ldm_x4(bh, skhi + base + t * 16 * SROW);
                ldm_x4(bl, sklo + base + t * 16 * SROW);
                #pragma unroll
                for (int t2 = 0; t2 < 2; t2++) {
                    float* d = sc[t * 2 + t2];
                    mma_bf16(d, qa_h[ks], &bh[t2 * 2]);
                    mma_bf16(d, qa_h[ks], &bl[t2 * 2]);
                    mma_bf16(d, qa_l[ks], &bh[t2 * 2]);
                }
            }
        }

        const unsigned long long w0 = adjb[(size_t)rr0 * 64 + kb];
        const unsigned long long w1 = adjb[(size_t)(rr0 + 8) * 64 + kb];
        uint32_t pa[4][4];
        #pragma unroll
        for (int f = 0; f < 8; f++) {
            const int cb = f * 8 + (lid & 3) * 2;
            const float s0 = ((w0 >> cb) & 1)       ? sc[f][0] : -102.0f;
            const float s1 = ((w0 >> (cb + 1)) & 1) ? sc[f][1] : -102.0f;
            const float s2 = ((w1 >> cb) & 1)       ? sc[f][2] : -102.0f;
            const float s3 = ((w1 >> (cb + 1)) & 1) ? sc[f][3] : -102.0f;
            const float p0 = fexp2b(s0), p1 = fexp2b(s1);
            const float p2 = fexp2b(s2), p3 = fexp2b(s3);
            lsum0 += p0 + p1; lsum1 += p2 + p3;
            __nv_bfloat162 x01 = __floats2bfloat162_rn(p0, p1);
            __nv_bfloat162 x23 = __floats2bfloat162_rn(p2, p3);
            const int j = f >> 1, oo = (f & 1) * 2;
            pa[j][oo]     = *reinterpret_cast<uint32_t*>(&x01);
            pa[j][oo + 1] = *reinterpret_cast<uint32_t*>(&x23);
        }

        #pragma unroll
        for (int ks = 0; ks < 4; ks++) {
            const uint32_t base = (uint32_t)(((ks >> 1) * 64 + b_row) * SROW
                                             + ((ks & 1) * 2 + b_sel) * 16);
            #pragma unroll
            for (int t = 0; t < 4; t++) {
                uint32_t bv[4];
                ldm_x4(bv, svt + base + t * 16 * SROW);
                mma_bf16(o_acc[t * 2],     pa[ks], &bv[0]);
                mma_bf16(o_acc[t * 2 + 1], pa[ks], &bv[2]);
            }
        }

        __syncthreads();
        if (kb < N_TOK / 64 - 1) {
            const int k0 = (kb + 1) * 64;
            #pragma unroll
            for (int i = 0; i < 2; i++) {
                const int idx = tid + i * 256;
                const int row = idx >> 3, ch = (idx >> 2) & 1, u = idx & 3;
                const uint32_t doff = (uint32_t)((ch * 64 + row) * SROW + u * 16);
                cp16(skhi + doff, khi + hoff + (size_t)(k0 + row) * 64 + ch * 32 + u * 8);
                cp16(sklo + doff, klo + hoff + (size_t)(k0 + row) * 64 + ch * 32 + u * 8);
                cp16(svt  + doff, vt  + hoff + (size_t)row * N_TOK + k0 + ch * 32 + u * 8);
            }
            asm volatile("cp.async.commit_group;");
        }
    }

    lsum0 += __shfl_xor_sync(0xffffffffu, lsum0, 1);
    lsum0 += __shfl_xor_sync(0xffffffffu, lsum0, 2);
    lsum1 += __shfl_xor_sync(0xffffffffu, lsum1, 1);
    lsum1 += __shfl_xor_sync(0xffffffffu, lsum1, 2);
    const float inv0 = 1.0f / lsum0, inv1 = 1.0f / lsum1;
    const int col0 = h * DKH + (lid & 3) * 2;
    #pragma unroll
    for (int f = 0; f < 8; f++) {
        uint32_t h0, l0, h1, l1;
        split2(o_acc[f][0] * inv0, o_acc[f][1] * inv0, h0, l0);
        split2(o_acc[f][2] * inv1, o_acc[f][3] * inv1, h1, l1);
        const size_t a0 = (size_t)rr0 * DM + col0 + f * 8;
        const size_t a1 = (size_t)(rr0 + 8) * DM + col0 + f * 8;
        *reinterpret_cast<uint32_t*>(cxhi + a0) = h0;
        *reinterpret_cast<uint32_t*>(cxlo + a0) = l0;
        *reinterpret_cast<uint32_t*>(cxhi + a1) = h1;
        *reinterpret_cast<uint32_t*>(cxlo + a1) = l1;
    }
}

// ---------------------------------------------------------------------------
// out = LayerNorm(x + r) * g + b; optionally also write hi/lo planes
// ---------------------------------------------------------------------------
template <bool PLANES>
__global__ __launch_bounds__(128) void ln_kernel(const float* __restrict__ x,
                                                 const float* __restrict__ r,
                                                 const float* __restrict__ g,
                                                 const float* __restrict__ b,
                                                 float* __restrict__ out,
                                                 __nv_bfloat16* __restrict__ phi,
                                                 __nv_bfloat16* __restrict__ plo)
{
    __shared__ float ws[4], ws2[4];
    const int row = blockIdx.x;
    const int tid = threadIdx.x;
    const int col = tid * 4;

    float4 xv = *reinterpret_cast<const float4*>(&x[(size_t)row * DM + col]);
    float4 rv = *reinterpret_cast<const float4*>(&r[(size_t)row * DM + col]);
    float v[4] = {xv.x + rv.x, xv.y + rv.y, xv.z + rv.z, xv.w + rv.w};

    float s = 0.0f, s2 = 0.0f;
    #pragma unroll
    for (int c = 0; c < 4; c++) { s += v[c]; s2 = fmaf(v[c], v[c], s2); }
    #pragma unroll
    for (int off = 16; off >= 1; off >>= 1) {
        s  += __shfl_xor_sync(0xffffffffu, s,  off);
        s2 += __shfl_xor_sync(0xffffffffu, s2, off);
    }
    const int wid = tid >> 5;
    if ((tid & 31) == 0) { ws[wid] = s; ws2[wid] = s2; }
    __syncthreads();
    const float S  = ws[0] + ws[1] + ws[2] + ws[3];
    const float S2 = ws2[0] + ws2[1] + ws2[2] + ws2[3];
    const float mean = S * (1.0f / DM);
    const float var  = S2 * (1.0f / DM) - mean * mean;
    const float rstd = rsqrtf(var + 1e-5f);

    float4 gv = *reinterpret_cast<const float4*>(&g[col]);
    float4 bv = *reinterpret_cast<const float4*>(&b[col]);
    float gr[4] = {gv.x, gv.y, gv.z, gv.w};
    float br[4] = {bv.x, bv.y, bv.z, bv.w};
    float4 ov; float* op = &ov.x;
    #pragma unroll
    for (int c = 0; c < 4; c++)
        op[c] = (v[c] - mean) * rstd * gr[c] + br[c];
    *reinterpret_cast<float4*>(&out[(size_t)row * DM + col]) = ov;
    if (PLANES) {
        uint32_t h0, l0, h1, l1;
        split2(ov.x, ov.y, h0, l0);
        split2(ov.z, ov.w, h1, l1);
        *reinterpret_cast<uint32_t*>(phi + (size_t)row * DM + col)     = h0;
        *reinterpret_cast<uint32_t*>(plo + (size_t)row * DM + col)     = l0;
        *reinterpret_cast<uint32_t*>(phi + (size_t)row * DM + col + 2) = h1;
        *reinterpret_cast<uint32_t*>(plo + (size_t)row * DM + col + 2) = l1;
    }
}

// ---------------------------------------------------------------------------
extern "C" void kernel_launch(void* const* d_in, const int* in_sizes, int n_in,
                              void* d_out, int out_size)
{
    const float* h    = (const float*)d_in[0];
    const int*   adj  = (const int*)d_in[1];
    const float* Wq   = (const float*)d_in[2];
    const float* bq   = (const float*)d_in[3];
    const float* Wk   = (const float*)d_in[4];
    const float* bk   = (const float*)d_in[5];
    const float* Wv   = (const float*)d_in[6];
    const float* bv   = (const float*)d_in[7];
    const float* Wo   = (const float*)d_in[8];
    const float* bo   = (const float*)d_in[9];
    const float* W1   = (const float*)d_in[10];
    const float* b1   = (const float*)d_in[11];
    const float* W2   = (const float*)d_in[12];
    const float* b2   = (const float*)d_in[13];
    const float* ln1g = (const float*)d_in[14];
    const float* ln1b = (const float*)d_in[15];
    const float* ln2g = (const float*)d_in[16];
    const float* ln2b = (const float*)d_in[17];
    float* out = (float*)d_out;

    float *Vd, *tmp, *h1;
    cudaGetSymbolAddress((void**)&Vd,  g_V);
    cudaGetSymbolAddress((void**)&tmp, g_tmp);
    cudaGetSymbolAddress((void**)&h1,  g_h1);

    __nv_bfloat16 *hb_hi, *hb_lo, *cx_hi, *cx_lo, *h1_hi, *h1_lo, *ff_hi, *ff_lo, *w_hi, *w_lo;
    __nv_bfloat16 *qs_hi, *qs_lo, *ks_hi, *ks_lo, *vtp;
    unsigned long long* adjb;
    cudaGetSymbolAddress((void**)&hb_hi, g_hb_hi);
    cudaGetSymbolAddress((void**)&hb_lo, g_hb_lo);
    cudaGetSymbolAddress((void**)&cx_hi, g_cx_hi);
    cudaGetSymbolAddress((void**)&cx_lo, g_cx_lo);
    cudaGetSymbolAddress((void**)&h1_hi, g_h1_hi);
    cudaGetSymbolAddress((void**)&h1_lo, g_h1_lo);
    cudaGetSymbolAddress((void**)&ff_hi, g_ff_hi);
    cudaGetSymbolAddress((void**)&ff_lo, g_ff_lo);
    cudaGetSymbolAddress((void**)&w_hi,  g_w_hi);
    cudaGetSymbolAddress((void**)&w_lo,  g_w_lo);
    cudaGetSymbolAddress((void**)&qs_hi, g_qs_hi);
    cudaGetSymbolAddress((void**)&qs_lo, g_qs_lo);
    cudaGetSymbolAddress((void**)&ks_hi, g_ks_hi);
    cudaGetSymbolAddress((void**)&ks_lo, g_ks_lo);
    cudaGetSymbolAddress((void**)&vtp,   g_vt);
    cudaGetSymbolAddress((void**)&adjb,  g_adjb);

    cudaFuncSetAttribute(gemm_mma_qkv,
                         cudaFuncAttributeMaxDynamicSharedMemorySize, GEMM_SMEM);
    cudaFuncSetAttribute(gemm_mma<false>,
                         cudaFuncAttributeMaxDynamicSharedMemorySize, GEMM_SMEM);
    cudaFuncSetAttribute(gemm_mma<true>,
                         cudaFuncAttributeMaxDynamicSharedMemorySize, GEMM_SMEM);

    const int ACT = N_TOK * DM;
    const float QSCALE = 1.4426950408889634f / 8.0f;   // log2(e)/sqrt(d_k)

    const dim3 blk(128);
    const dim3 gQKV(DM / 64, N_TOK / 128, 3);
    const dim3 gP(DM / 64, N_TOK / 128);
    const dim3 gF1(DFF / 64, N_TOK / 128);

    // launches ordered so attn_mma is the 6th launch (ncu -s 5 profiles it)
    pack_adj<<<(N_TOK * 64) / 256, 256>>>(adj, adjb);                       // 1
    convert_split<<<1024, 256>>>(h, hb_hi, hb_lo, ACT);                     // 2
    convert_w<<<2048, 256>>>(Wq, Wk, Wv, Wo, W1, W2, w_hi, w_lo);           // 3
    gemm_mma_qkv<<<gQKV, blk, GEMM_SMEM>>>(hb_hi, hb_lo, bq, bk, bv,        // 4
                                           qs_hi, qs_lo, ks_hi, ks_lo, Vd, QSCALE);
    convert_v_t<<<dim3(N_TOK / 64, NH), 256>>>(Vd, vtp);                    // 5
    attn_mma<<<dim3(N_TOK / 128, NH), 256>>>(qs_hi, qs_lo, ks_hi, ks_lo,    // 6
                                             vtp, adjb, cx_hi, cx_lo);
    gemm_mma<false><<<gP, blk, GEMM_SMEM>>>(cx_hi, cx_lo, w_hi + WOFF_O, w_lo + WOFF_O,
                                            bo, tmp, nullptr, nullptr, 1.0f, DM, DM, OUT_F32);
    ln_kernel<true><<<N_TOK, 128>>>(h, tmp, ln1g, ln1b, h1, h1_hi, h1_lo);
    gemm_mma<true><<<gF1, blk, GEMM_SMEM>>>(h1_hi, h1_lo, w_hi + WOFF_1, w_lo + WOFF_1,
                                            b1, nullptr, ff_hi, ff_lo, 1.0f, DFF, DM, OUT_PLANES);
    gemm_mma<false><<<gP, blk, GEMM_SMEM>>>(ff_hi, ff_lo, w_hi + WOFF_2, w_lo + WOFF_2,
                                            b2, tmp, nullptr, nullptr, 1.0f, DM, DFF, OUT_F32);
    ln_kernel<false><<<N_TOK, 128>>>(h1, tmp, ln2g, ln2b, out, nullptr, nullptr);
}

// round 14
// speedup vs baseline: 1.2888x; 1.2439x over previous
#include <cuda_runtime.h>
#include <cuda_bf16.h>
#include <cuda_fp16.h>
#include <cstdint>

#define N_TOK 4096
#define DM    512
#define NH    8
#define DKH   64
#define DFF   2048

// ---------------- scratch (device globals; no runtime allocation) ----------
__device__ float g_V[N_TOK * DM];
__device__ float g_tmp[N_TOK * DM];
__device__ float g_h1[N_TOK * DM];

// fp16 activation planes (hi only) and fp16 weight planes (hi+lo)
__device__ __half g_hb[N_TOK * DM];
__device__ __half g_cx[N_TOK * DM];
__device__ __half g_h1p[N_TOK * DM];
__device__ __half g_ffp[(size_t)N_TOK * DFF];
#define WOFF_Q  0
#define WOFF_K  (512 * 512)
#define WOFF_V  (2 * 512 * 512)
#define WOFF_O  (3 * 512 * 512)
#define WOFF_1  (4 * 512 * 512)
#define WOFF_2  (4 * 512 * 512 + 2048 * 512)
#define WTOT    (4 * 512 * 512 + 2 * 2048 * 512)
__device__ __half g_w_hi[WTOT], g_w_lo[WTOT];

// attention (bf16): Q hi-only, K hi+lo, per-head [h][tok][64]; V^T [h][d][tok]
__device__ __nv_bfloat16 g_qs_hi[NH * N_TOK * DKH];
__device__ __nv_bfloat16 g_ks_hi[NH * N_TOK * DKH], g_ks_lo[NH * N_TOK * DKH];
__device__ __nv_bfloat16 g_vt[NH * DKH * N_TOK];
__device__ unsigned long long g_adjb[N_TOK * (N_TOK / 64)];

// epilogue output modes
#define OUT_F32   0
#define OUT_H16   1   // fp16 hi-only plane (activations)
#define OUT_QHEAD 2   // bf16 per-head hi-only, scaled
#define OUT_KHEAD 3   // bf16 per-head hi+lo

// ===================== low-level helpers ==================================
__device__ __forceinline__ uint32_t smem_u32(const void* p) {
    uint32_t a;
    asm("{ .reg .u64 t; cvta.to.shared.u64 t, %1; cvt.u32.u64 %0, t; }"
        : "=r"(a) : "l"(p));
    return a;
}
__device__ __forceinline__ void cp16(uint32_t dst, const void* src) {
    asm volatile("cp.async.cg.shared.global [%0], [%1], 16;" :: "r"(dst), "l"(src));
}
__device__ __forceinline__ void ldm_x4(uint32_t* r, uint32_t addr) {
    asm volatile("ldmatrix.sync.aligned.m8n8.x4.shared.b16 {%0,%1,%2,%3}, [%4];"
                 : "=r"(r[0]), "=r"(r[1]), "=r"(r[2]), "=r"(r[3]) : "r"(addr));
}
__device__ __forceinline__ void mma_bf16(float* d, const uint32_t* a, const uint32_t* b) {
    asm volatile("mma.sync.aligned.m16n8k16.row.col.f32.bf16.bf16.f32 "
                 "{%0,%1,%2,%3},{%4,%5,%6,%7},{%8,%9},{%0,%1,%2,%3};"
                 : "+f"(d[0]), "+f"(d[1]), "+f"(d[2]), "+f"(d[3])
                 : "r"(a[0]), "r"(a[1]), "r"(a[2]), "r"(a[3]),
                   "r"(b[0]), "r"(b[1]));
}
__device__ __forceinline__ void mma_fp16(float* d, const uint32_t* a, const uint32_t* b) {
    asm volatile("mma.sync.aligned.m16n8k16.row.col.f32.f16.f16.f32 "
                 "{%0,%1,%2,%3},{%4,%5,%6,%7},{%8,%9},{%0,%1,%2,%3};"
                 : "+f"(d[0]), "+f"(d[1]), "+f"(d[2]), "+f"(d[3])
                 : "r"(a[0]), "r"(a[1]), "r"(a[2]), "r"(a[3]),
                   "r"(b[0]), "r"(b[1]));
}
__device__ __forceinline__ float fexp2b(float s) {
    const float C1 = 12582904.0f;                 // 1.5*2^23 - 8
    float t  = s + C1;
    float v  = t - C1;
    float zf = s - v;
    int   zi = __float_as_int(t) - 0x4B400000;
    float p = fmaf(zf, 0.00961813f, 0.05550411f);
    p = fmaf(zf, p, 0.24022651f);
    p = fmaf(zf, p, 0.69314718f);
    p = fmaf(zf, p, 1.0f);
    return __int_as_float(__float_as_int(p) + (zi << 23));
}
// bf16 split (attention K planes)
__device__ __forceinline__ void split2b(float x, float y, uint32_t& hi, uint32_t& lo) {
    __nv_bfloat162 h = __floats2bfloat162_rn(x, y);
    float hx = __bfloat162float(h.x), hy = __bfloat162float(h.y);
    __nv_bfloat162 l = __floats2bfloat162_rn(x - hx, y - hy);
    hi = *reinterpret_cast<uint32_t*>(&h);
    lo = *reinterpret_cast<uint32_t*>(&l);
}
__device__ __forceinline__ uint32_t pack_b2(float x, float y) {
    __nv_bfloat162 h = __floats2bfloat162_rn(x, y);
    return *reinterpret_cast<uint32_t*>(&h);
}
// fp16 split / pack
__device__ __forceinline__ void split2h(float x, float y, uint32_t& hi, uint32_t& lo) {
    __half2 h = __floats2half2_rn(x, y);
    float hx = __half2float(__low2half(h)), hy = __half2float(__high2half(h));
    __half2 l = __floats2half2_rn(x - hx, y - hy);
    hi = *reinterpret_cast<uint32_t*>(&h);
    lo = *reinterpret_cast<uint32_t*>(&l);
}
__device__ __forceinline__ uint32_t pack_h2(float x, float y) {
    __half2 h = __floats2half2_rn(x, y);
    return *reinterpret_cast<uint32_t*>(&h);
}

// ===================== element-wise prep kernels ==========================
// h (fp32) -> fp16 hi-only plane
__global__ __launch_bounds__(256) void convert_h(const float* __restrict__ in,
                                                 __half* __restrict__ hi, int n)
{
    for (int i = (blockIdx.x * 256 + threadIdx.x) * 4; i < n; i += gridDim.x * 1024) {
        float4 v = *reinterpret_cast<const float4*>(in + i);
        *reinterpret_cast<uint32_t*>(hi + i)     = pack_h2(v.x, v.y);
        *reinterpret_cast<uint32_t*>(hi + i + 2) = pack_h2(v.z, v.w);
    }
}

// all 6 weights -> fp16 hi/lo planes, one launch
__global__ __launch_bounds__(256) void convert_w(const float* __restrict__ Wq,
                                                 const float* __restrict__ Wk,
                                                 const float* __restrict__ Wv,
                                                 const float* __restrict__ Wo,
                                                 const float* __restrict__ W1,
                                                 const float* __restrict__ W2,
                                                 __half* __restrict__ hi,
                                                 __half* __restrict__ lo)
{
    const int WSQ = 512 * 512, WFF = 2048 * 512;
    for (int i = (blockIdx.x * 256 + threadIdx.x) * 4; i < WTOT; i += gridDim.x * 1024) {
        const float* src; int off;
        if (i < 4 * WSQ)            { int r = i / WSQ; off = i - r * WSQ;
                                      src = (r == 0) ? Wq : (r == 1) ? Wk : (r == 2) ? Wv : Wo; }
        else if (i < 4 * WSQ + WFF) { src = W1; off = i - 4 * WSQ; }
        else                        { src = W2; off = i - 4 * WSQ - WFF; }
        float4 v = *reinterpret_cast<const float4*>(src + off);
        uint32_t h0, l0, h1, l1;
        split2h(v.x, v.y, h0, l0);
        split2h(v.z, v.w, h1, l1);
        *reinterpret_cast<uint32_t*>(hi + i)     = h0;
        *reinterpret_cast<uint32_t*>(hi + i + 2) = h1;
        *reinterpret_cast<uint32_t*>(lo + i)     = l0;
        *reinterpret_cast<uint32_t*>(lo + i + 2) = l1;
    }
}

__global__ __launch_bounds__(256) void convert_v_t(const float* __restrict__ V,
                                                   __nv_bfloat16* __restrict__ vt)
{
    __shared__ float sm[64][65];
    const int h = blockIdx.y, t0 = blockIdx.x * 64;
    const int tid = threadIdx.x;
    for (int i = tid; i < 1024; i += 256) {
        int r = i >> 4, c4 = (i & 15) * 4;
        float4 v = *reinterpret_cast<const float4*>(&V[(size_t)(t0 + r) * DM + h * DKH + c4]);
        sm[c4][r] = v.x; sm[c4 + 1][r] = v.y; sm[c4 + 2][r] = v.z; sm[c4 + 3][r] = v.w;
    }
    __syncthreads();
    for (int i = tid; i < 2048; i += 256) {
        int d = i >> 5, pr = i & 31;
        __nv_bfloat162 b = __floats2bfloat162_rn(sm[d][2 * pr], sm[d][2 * pr + 1]);
        *reinterpret_cast<__nv_bfloat162*>(
            vt + (size_t)h * (DKH * N_TOK) + (size_t)d * N_TOK + t0 + 2 * pr) = b;
    }
}

__global__ __launch_bounds__(256) void pack_adj(const int* __restrict__ adj,
                                                unsigned long long* __restrict__ bits)
{
    int gid = blockIdx.x * 256 + threadIdx.x;
    int r = gid >> 6, w = gid & 63;
    const int4* p = reinterpret_cast<const int4*>(adj + (size_t)r * N_TOK + w * 64);
    unsigned long long b = 0;
    #pragma unroll
    for (int i = 0; i < 16; i++) {
        int4 a = p[i];
        if (a.x) b |= 1ull << (i * 4 + 0);
        if (a.y) b |= 1ull << (i * 4 + 1);
        if (a.z) b |= 1ull << (i * 4 + 2);
        if (a.w) b |= 1ull << (i * 4 + 3);
    }
    if ((r >> 6) == w) b |= 1ull << (r & 63);
    bits[gid] = b;
}

// ===================== fp16 2-term GEMM (128x64 tile, pipelined) ==========
// C = A * B^T + bias.  acc = Ah*Bh + Ah*Bl  (activation residual dropped)
#define SROW 80
#define GS_AH 0
#define GS_BH 10240
#define GS_BL 15360
#define GS_STAGE 20480
#define GEMM_SMEM (2 * GS_STAGE)

extern __shared__ __align__(128) uint8_t g_dyn[];

__device__ __forceinline__ void gemm_load_chunk(
    uint32_t sbase,
    const __half* gA, const __half* gB_hi, const __half* gB_lo,
    int K, int c, int tid)
{
    const int u  = tid & 3;
    const int gk = c * 32 + u * 8;
    #pragma unroll
    for (int i = 0; i < 4; i++) {      // A: 128 rows
        const int row = (tid >> 2) + i * 32;
        cp16(sbase + GS_AH + (uint32_t)(row * SROW + u * 16),
             gA + (size_t)row * K + gk);
    }
    #pragma unroll
    for (int i = 0; i < 2; i++) {      // B: 64 rows, hi+lo
        const int row = (tid >> 2) + i * 32;
        const uint32_t doff = (uint32_t)(row * SROW + u * 16);
        const size_t go = (size_t)row * K + gk;
        cp16(sbase + GS_BH + doff, gB_hi + go);
        cp16(sbase + GS_BL + doff, gB_lo + go);
    }
    asm volatile("cp.async.commit_group;");
}

template <bool RELU>
__device__ __forceinline__ void gemm_mma_body(const __half* __restrict__ A,
                                              const __half* __restrict__ Bhi,
                                              const __half* __restrict__ Blo,
                                              const float* __restrict__ bias,
                                              float* __restrict__ C,
                                              __half* __restrict__ Ph,
                                              __nv_bfloat16* __restrict__ H1,
                                              __nv_bfloat16* __restrict__ H2,
                                              float oscale,
                                              int Nn, int K, int mode)
{
    const int tid = threadIdx.x, lid = tid & 31, wid = tid >> 5;
    const int wm  = wid * 32;
    const int m0  = blockIdx.y * 128, n0 = blockIdx.x * 64;

    const uint32_t sb0 = smem_u32(g_dyn);
    const uint32_t sb[2] = {sb0, sb0 + GS_STAGE};

    const __half* gA    = A   + (size_t)m0 * K;
    const __half* gB_hi = Bhi + (size_t)n0 * K;
    const __half* gB_lo = Blo + (size_t)n0 * K;

    const int a_row = lid & 15;
    const int a_sel = lid >> 4;
    const int b_row = ((lid >> 4) & 1) * 8 + (lid & 7);
    const int b_sel = (lid >> 3) & 1;

    float acc[2][8][4] = {};

    const int nch = K >> 5;
    gemm_load_chunk(sb[0], gA, gB_hi, gB_lo, K, 0, tid);
    if (nch > 1)
        gemm_load_chunk(sb[1], gA, gB_hi, gB_lo, K, 1, tid);

    for (int c = 0; c < nch; c++) {
        if (c == nch - 1) asm volatile("cp.async.wait_group 0;" ::: "memory");
        else              asm volatile("cp.async.wait_group 1;" ::: "memory");
        __syncthreads();

        const uint32_t st = sb[c & 1];
        #pragma unroll
        for (int ks = 0; ks < 2; ks++) {
            uint32_t ah[2][4];
            #pragma unroll
            for (int mg = 0; mg < 2; mg++) {
                const uint32_t aoff = (uint32_t)((wm + mg * 16 + a_row) * SROW
                                                 + (ks * 2 + a_sel) * 16);
                ldm_x4(ah[mg], st + GS_AH + aoff);
            }
            uint32_t bh[4][4], bl[4][4];
            #pragma unroll
            for (int t = 0; t < 4; t++) {
                const uint32_t boff = (uint32_t)((t * 16 + b_row) * SROW
                                                 + (ks * 2 + b_sel) * 16);
                ldm_x4(bh[t], st + GS_BH + boff);
                ldm_x4(bl[t], st + GS_BL + boff);
            }
            // pass 1: Ah * Bh (16 independent accumulators)
            #pragma unroll
            for (int t = 0; t < 4; t++)
                #pragma unroll
                for (int mg = 0; mg < 2; mg++)
                    #pragma unroll
                    for (int t2 = 0; t2 < 2; t2++)
                        mma_fp16(acc[mg][t * 2 + t2], ah[mg], &bh[t][t2 * 2]);
            // pass 2: Ah * Bl
            #pragma unroll
            for (int t = 0; t < 4; t++)
                #pragma unroll
                for (int mg = 0; mg < 2; mg++)
                    #pragma unroll
                    for (int t2 = 0; t2 < 2; t2++)
                        mma_fp16(acc[mg][t * 2 + t2], ah[mg], &bl[t][t2 * 2]);
        }
        __syncthreads();
        if (c + 2 < nch)
            gemm_load_chunk(sb[c & 1], gA, gB_hi, gB_lo, K, c + 2, tid);
    }

    // epilogue
    const int cbase = n0 + (lid & 3) * 2;
    #pragma unroll
    for (int mg = 0; mg < 2; mg++) {
        const int rr0 = m0 + wm + mg * 16 + (lid >> 2);
        #pragma unroll
        for (int f = 0; f < 8; f++) {
            const int col = cbase + f * 8;
            const float bx = bias[col], by = bias[col + 1];
            float v00 = acc[mg][f][0] + bx, v01 = acc[mg][f][1] + by;
            float v10 = acc[mg][f][2] + bx, v11 = acc[mg][f][3] + by;
            if (RELU) {
                v00 = fmaxf(v00, 0.0f); v01 = fmaxf(v01, 0.0f);
                v10 = fmaxf(v10, 0.0f); v11 = fmaxf(v11, 0.0f);
            }
            if (mode == OUT_F32) {
                *reinterpret_cast<float2*>(C + (size_t)rr0 * Nn + col)       = make_float2(v00, v01);
                *reinterpret_cast<float2*>(C + (size_t)(rr0 + 8) * Nn + col) = make_float2(v10, v11);
            } else if (mode == OUT_H16) {
                *reinterpret_cast<uint32_t*>(Ph + (size_t)rr0 * Nn + col)       = pack_h2(v00, v01);
                *reinterpret_cast<uint32_t*>(Ph + (size_t)(rr0 + 8) * Nn + col) = pack_h2(v10, v11);
            } else if (mode == OUT_QHEAD) {     // bf16 per-head hi-only, scaled
                const int hh = col >> 6, d = col & 63;
                const size_t base0 = (size_t)hh * (N_TOK * DKH) + (size_t)rr0 * DKH + d;
                *reinterpret_cast<uint32_t*>(H1 + base0)           = pack_b2(v00 * oscale, v01 * oscale);
                *reinterpret_cast<uint32_t*>(H1 + base0 + 8 * DKH) = pack_b2(v10 * oscale, v11 * oscale);
            } else {                             // OUT_KHEAD: bf16 per-head hi+lo
                const int hh = col >> 6, d = col & 63;
                const size_t base0 = (size_t)hh * (N_TOK * DKH) + (size_t)rr0 * DKH + d;
                const size_t base1 = base0 + 8 * DKH;
                uint32_t h0, l0, h1, l1;
                split2b(v00, v01, h0, l0);
                split2b(v10, v11, h1, l1);
                *reinterpret_cast<uint32_t*>(H1 + base0) = h0;
                *reinterpret_cast<uint32_t*>(H2 + base0) = l0;
                *reinterpret_cast<uint32_t*>(H1 + base1) = h1;
                *reinterpret_cast<uint32_t*>(H2 + base1) = l1;
            }
        }
    }
}

template <bool RELU>
__global__ __launch_bounds__(128) void gemm_mma(const __half* __restrict__ A,
                                                const __half* __restrict__ Bhi,
                                                const __half* __restrict__ Blo,
                                                const float* __restrict__ bias,
                                                float* C, __half* Ph,
                                                int Nn, int K, int mode)
{
    gemm_mma_body<RELU>(A, Bhi, Blo, bias, C, Ph, nullptr, nullptr, 1.0f, Nn, K, mode);
}

__global__ __launch_bounds__(128) void gemm_mma_qkv(const __half* __restrict__ A,
                                                    const float* __restrict__ bq,
                                                    const float* __restrict__ bk,
                                                    const float* __restrict__ bv,
                                                    __nv_bfloat16* qhi,
                                                    __nv_bfloat16* khi, __nv_bfloat16* klo,
                                                    float* Vo, float qscale)
{
    if (blockIdx.z == 0)
        gemm_mma_body<false>(A, g_w_hi + WOFF_Q, g_w_lo + WOFF_Q, bq,
                             nullptr, nullptr, qhi, nullptr, qscale, DM, DM, OUT_QHEAD);
    else if (blockIdx.z == 1)
        gemm_mma_body<false>(A, g_w_hi + WOFF_K, g_w_lo + WOFF_K, bk,
                             nullptr, nullptr, khi, klo, 1.0f, DM, DM, OUT_KHEAD);
    else
        gemm_mma_body<false>(A, g_w_hi + WOFF_V, g_w_lo + WOFF_V, bv,
                             Vo, nullptr, nullptr, nullptr, 1.0f, DM, DM, OUT_F32);
}

// ===================== tensor-core flash attention ========================
// q-tile 128, 256 threads. QK 2-term (Qh*Kh + Qh*Kl), PV bf16. cx -> fp16 plane.
__global__ __launch_bounds__(256, 1) void attn_mma(
    const __nv_bfloat16* __restrict__ qhi,
    const __nv_bfloat16* __restrict__ khi, const __nv_bfloat16* __restrict__ klo,
    const __nv_bfloat16* __restrict__ vt,
    const unsigned long long* __restrict__ adjb,
    __half* __restrict__ cxh)
{
    __shared__ __align__(128) uint8_t s_khi[2 * 64 * SROW];
    __shared__ __align__(128) uint8_t s_klo[2 * 64 * SROW];
    __shared__ __align__(128) uint8_t s_vt [2 * 64 * SROW];

    const int tid = threadIdx.x, lid = tid & 31, wid = tid >> 5;
    const int h = blockIdx.y, q0 = blockIdx.x * 128;
    const int wm = wid * 16;
    const size_t hoff = (size_t)h * (N_TOK * DKH);

    const uint32_t skhi = smem_u32(s_khi), sklo = smem_u32(s_klo), svt = smem_u32(s_vt);

    uint32_t qa_h[4][4];
    const int rr0 = q0 + wm + (lid >> 2);
    {
        const int cc = (lid & 3) * 2;
        #pragma unroll
        for (int ks = 0; ks < 4; ks++) {
            const size_t o0 = hoff + (size_t)rr0 * 64 + ks * 16 + cc;
            const size_t o1 = hoff + (size_t)(rr0 + 8) * 64 + ks * 16 + cc;
            qa_h[ks][0] = *reinterpret_cast<const uint32_t*>(qhi + o0);
            qa_h[ks][1] = *reinterpret_cast<const uint32_t*>(qhi + o1);
            qa_h[ks][2] = *reinterpret_cast<const uint32_t*>(qhi + o0 + 8);
            qa_h[ks][3] = *reinterpret_cast<const uint32_t*>(qhi + o1 + 8);
        }
    }

    const int b_row = ((lid >> 4) & 1) * 8 + (lid & 7);
    const int b_sel = (lid >> 3) & 1;

    float o_acc[8][4] = {};
    float lsum0 = 0.0f, lsum1 = 0.0f;

    {
        #pragma unroll
        for (int i = 0; i < 2; i++) {
            const int idx = tid + i * 256;
            const int row = idx >> 3, ch = (idx >> 2) & 1, u = idx & 3;
            const uint32_t doff = (uint32_t)((ch * 64 + row) * SROW + u * 16);
            cp16(skhi + doff, khi + hoff + (size_t)row * 64 + ch * 32 + u * 8);
            cp16(sklo + doff, klo + hoff + (size_t)row * 64 + ch * 32 + u * 8);
            cp16(svt  + doff, vt  + hoff + (size_t)row * N_TOK + ch * 32 + u * 8);
        }
        asm volatile("cp.async.commit_group;");
    }

    for (int kb = 0; kb < N_TOK / 64; kb++) {
        asm volatile("cp.async.wait_group 0;" ::: "memory");
        __syncthreads();

        float sc[8][4] = {};
        #pragma unroll
        for (int ks = 0; ks < 4; ks++) {
            const uint32_t base = (uint32_t)(((ks >> 1) * 64 + b_row) * SROW
                                             + ((ks & 1) * 2 + b_sel) * 16);
            #pragma unroll
            for (int t = 0; t < 4; t++) {
                uint32_t bh[4], bl[4];
                ldm_x4(bh, skhi + base + t * 16 * SROW);
                ldm_x4(bl, sklo + base + t * 16 * SROW);
                #pragma unroll
                for (int t2 = 0; t2 < 2; t2++) {
                    float* d = sc[t * 2 + t2];
                    mma_bf16(d, qa_h[ks], &bh[t2 * 2]);
                    mma_bf16(d, qa_h[ks], &bl[t2 * 2]);
                }
            }
        }

        const unsigned long long w0 = adjb[(size_t)rr0 * 64 + kb];
        const unsigned long long w1 = adjb[(size_t)(rr0 + 8) * 64 + kb];
        uint32_t pa[4][4];
        #pragma unroll
        for (int f = 0; f < 8; f++) {
            const int cb = f * 8 + (lid & 3) * 2;
            const float s0 = ((w0 >> cb) & 1)       ? sc[f][0] : -102.0f;
            const float s1 = ((w0 >> (cb + 1)) & 1) ? sc[f][1] : -102.0f;
            const float s2 = ((w1 >> cb) & 1)       ? sc[f][2] : -102.0f;
            const float s3 = ((w1 >> (cb + 1)) & 1) ? sc[f][3] : -102.0f;
            const float p0 = fexp2b(s0), p1 = fexp2b(s1);
            const float p2 = fexp2b(s2), p3 = fexp2b(s3);
            lsum0 += p0 + p1; lsum1 += p2 + p3;
            const int j = f >> 1, oo = (f & 1) * 2;
            pa[j][oo]     = pack_b2(p0, p1);
            pa[j][oo + 1] = pack_b2(p2, p3);
        }

        #pragma unroll
        for (int ks = 0; ks < 4; ks++) {
            const uint32_t base = (uint32_t)(((ks >> 1) * 64 + b_row) * SROW
                                             + ((ks & 1) * 2 + b_sel) * 16);
            #pragma unroll
            for (int t = 0; t < 4; t++) {
                uint32_t bv[4];
                ldm_x4(bv, svt + base + t * 16 * SROW);
                mma_bf16(o_acc[t * 2],     pa[ks], &bv[0]);
                mma_bf16(o_acc[t * 2 + 1], pa[ks], &bv[2]);
            }
        }

        __syncthreads();
        if (kb < N_TOK / 64 - 1) {
            const int k0 = (kb + 1) * 64;
            #pragma unroll
            for (int i = 0; i < 2; i++) {
                const int idx = tid + i * 256;
                const int row = idx >> 3, ch = (idx >> 2) & 1, u = idx & 3;
                const uint32_t doff = (uint32_t)((ch * 64 + row) * SROW + u * 16);
                cp16(skhi + doff, khi + hoff + (size_t)(k0 + row) * 64 + ch * 32 + u * 8);
                cp16(sklo + doff, klo + hoff + (size_t)(k0 + row) * 64 + ch * 32 + u * 8);
                cp16(svt  + doff, vt  + hoff + (size_t)row * N_TOK + k0 + ch * 32 + u * 8);
            }
            asm volatile("cp.async.commit_group;");
        }
    }

    lsum0 += __shfl_xor_sync(0xffffffffu, lsum0, 1);
    lsum0 += __shfl_xor_sync(0xffffffffu, lsum0, 2);
    lsum1 += __shfl_xor_sync(0xffffffffu, lsum1, 1);
    lsum1 += __shfl_xor_sync(0xffffffffu, lsum1, 2);
    const float inv0 = 1.0f / lsum0, inv1 = 1.0f / lsum1;
    const int col0 = h * DKH + (lid & 3) * 2;
    #pragma unroll
    for (int f = 0; f < 8; f++) {
        const size_t a0 = (size_t)rr0 * DM + col0 + f * 8;
        const size_t a1 = (size_t)(rr0 + 8) * DM + col0 + f * 8;
        *reinterpret_cast<uint32_t*>(cxh + a0) = pack_h2(o_acc[f][0] * inv0, o_acc[f][1] * inv0);
        *reinterpret_cast<uint32_t*>(cxh + a1) = pack_h2(o_acc[f][2] * inv1, o_acc[f][3] * inv1);
    }
}

// ---------------------------------------------------------------------------
// out = LayerNorm(x + r) * g + b; optionally also fp16 hi-only plane
// ---------------------------------------------------------------------------
template <bool PLANES>
__global__ __launch_bounds__(128) void ln_kernel(const float* __restrict__ x,
                                                 const float* __restrict__ r,
                                                 const float* __restrict__ g,
                                                 const float* __restrict__ b,
                                                 float* __restrict__ out,
                                                 __half* __restrict__ ph)
{
    __shared__ float ws[4], ws2[4];
    const int row = blockIdx.x;
    const int tid = threadIdx.x;
    const int col = tid * 4;

    float4 xv = *reinterpret_cast<const float4*>(&x[(size_t)row * DM + col]);
    float4 rv = *reinterpret_cast<const float4*>(&r[(size_t)row * DM + col]);
    float v[4] = {xv.x + rv.x, xv.y + rv.y, xv.z + rv.z, xv.w + rv.w};

    float s = 0.0f, s2 = 0.0f;
    #pragma unroll
    for (int c = 0; c < 4; c++) { s += v[c]; s2 = fmaf(v[c], v[c], s2); }
    #pragma unroll
    for (int off = 16; off >= 1; off >>= 1) {
        s  += __shfl_xor_sync(0xffffffffu, s,  off);
        s2 += __shfl_xor_sync(0xffffffffu, s2, off);
    }
    const int wid = tid >> 5;
    if ((tid & 31) == 0) { ws[wid] = s; ws2[wid] = s2; }
    __syncthreads();
    const float S  = ws[0] + ws[1] + ws[2] + ws[3];
    const float S2 = ws2[0] + ws2[1] + ws2[2] + ws2[3];
    const float mean = S * (1.0f / DM);
    const float var  = S2 * (1.0f / DM) - mean * mean;
    const float rstd = rsqrtf(var + 1e-5f);

    float4 gv = *reinterpret_cast<const float4*>(&g[col]);
    float4 bv = *reinterpret_cast<const float4*>(&b[col]);
    float gr[4] = {gv.x, gv.y, gv.z, gv.w};
    float br[4] = {bv.x, bv.y, bv.z, bv.w};
    float4 ov; float* op = &ov.x;
    #pragma unroll
    for (int c = 0; c < 4; c++)
        op[c] = (v[c] - mean) * rstd * gr[c] + br[c];
    *reinterpret_cast<float4*>(&out[(size_t)row * DM + col]) = ov;
    if (PLANES) {
        *reinterpret_cast<uint32_t*>(ph + (size_t)row * DM + col)     = pack_h2(ov.x, ov.y);
        *reinterpret_cast<uint32_t*>(ph + (size_t)row * DM + col + 2) = pack_h2(ov.z, ov.w);
    }
}

// ---------------------------------------------------------------------------
extern "C" void kernel_launch(void* const* d_in, const int* in_sizes, int n_in,
                              void* d_out, int out_size)
{
    const float* h    = (const float*)d_in[0];
    const int*   adj  = (const int*)d_in[1];
    const float* Wq   = (const float*)d_in[2];
    const float* bq   = (const float*)d_in[3];
    const float* Wk   = (const float*)d_in[4];
    const float* bk   = (const float*)d_in[5];
    const float* Wv   = (const float*)d_in[6];
    const float* bv   = (const float*)d_in[7];
    const float* Wo   = (const float*)d_in[8];
    const float* bo   = (const float*)d_in[9];
    const float* W1   = (const float*)d_in[10];
    const float* b1   = (const float*)d_in[11];
    const float* W2   = (const float*)d_in[12];
    const float* b2   = (const float*)d_in[13];
    const float* ln1g = (const float*)d_in[14];
    const float* ln1b = (const float*)d_in[15];
    const float* ln2g = (const float*)d_in[16];
    const float* ln2b = (const float*)d_in[17];
    float* out = (float*)d_out;

    float *Vd, *tmp, *h1;
    cudaGetSymbolAddress((void**)&Vd,  g_V);
    cudaGetSymbolAddress((void**)&tmp, g_tmp);
    cudaGetSymbolAddress((void**)&h1,  g_h1);

    __half *hb, *cx, *h1p, *ffp, *w_hi, *w_lo;
    __nv_bfloat16 *qs_hi, *ks_hi, *ks_lo, *vtp;
    unsigned long long* adjb;
    cudaGetSymbolAddress((void**)&hb,   g_hb);
    cudaGetSymbolAddress((void**)&cx,   g_cx);
    cudaGetSymbolAddress((void**)&h1p,  g_h1p);
    cudaGetSymbolAddress((void**)&ffp,  g_ffp);
    cudaGetSymbolAddress((void**)&w_hi, g_w_hi);
    cudaGetSymbolAddress((void**)&w_lo, g_w_lo);
    cudaGetSymbolAddress((void**)&qs_hi, g_qs_hi);
    cudaGetSymbolAddress((void**)&ks_hi, g_ks_hi);
    cudaGetSymbolAddress((void**)&ks_lo, g_ks_lo);
    cudaGetSymbolAddress((void**)&vtp,   g_vt);
    cudaGetSymbolAddress((void**)&adjb,  g_adjb);

    cudaFuncSetAttribute(gemm_mma_qkv,
                         cudaFuncAttributeMaxDynamicSharedMemorySize, GEMM_SMEM);
    cudaFuncSetAttribute(gemm_mma<false>,
                         cudaFuncAttributeMaxDynamicSharedMemorySize, GEMM_SMEM);
    cudaFuncSetAttribute(gemm_mma<true>,
                         cudaFuncAttributeMaxDynamicSharedMemorySize, GEMM_SMEM);

    const int ACT = N_TOK * DM;
    const float QSCALE = 1.4426950408889634f / 8.0f;   // log2(e)/sqrt(d_k)

    const dim3 blk(128);
    const dim3 gQKV(DM / 64, N_TOK / 128, 3);
    const dim3 gP(DM / 64, N_TOK / 128);
    const dim3 gF1(DFF / 64, N_TOK / 128);

    // launches ordered so attn_mma is the 6th launch (ncu -s 5 profiles it)
    pack_adj<<<(N_TOK * 64) / 256, 256>>>(adj, adjb);                       // 1
    convert_h<<<1024, 256>>>(h, hb, ACT);                                   // 2
    convert_w<<<2048, 256>>>(Wq, Wk, Wv, Wo, W1, W2, w_hi, w_lo);           // 3
    gemm_mma_qkv<<<gQKV, blk, GEMM_SMEM>>>(hb, bq, bk, bv,                  // 4
                                           qs_hi, ks_hi, ks_lo, Vd, QSCALE);
    convert_v_t<<<dim3(N_TOK / 64, NH), 256>>>(Vd, vtp);                    // 5
    attn_mma<<<dim3(N_TOK / 128, NH), 256>>>(qs_hi, ks_hi, ks_lo,           // 6
                                             vtp, adjb, cx);
    gemm_mma<false><<<gP, blk, GEMM_SMEM>>>(cx, w_hi + WOFF_O, w_lo + WOFF_O,
                                            bo, tmp, nullptr, DM, DM, OUT_F32);
    ln_kernel<true><<<N_TOK, 128>>>(h, tmp, ln1g, ln1b, h1, h1p);
    gemm_mma<true><<<gF1, blk, GEMM_SMEM>>>(h1p, w_hi + WOFF_1, w_lo + WOFF_1,
                                            b1, nullptr, ffp, DFF, DM, OUT_H16);
    gemm_mma<false><<<gP, blk, GEMM_SMEM>>>(ffp, w_hi + WOFF_2, w_lo + WOFF_2,
                                            b2, tmp, nullptr, DM, DFF, OUT_F32);
    ln_kernel<false><<<N_TOK, 128>>>(h1, tmp, ln2g, ln2b, out, nullptr);
}

// round 15
// speedup vs baseline: 1.4634x; 1.1355x over previous
#include <cuda_runtime.h>
#include <cuda_bf16.h>
#include <cuda_fp16.h>
#include <cstdint>

#define N_TOK 4096
#define DM    512
#define NH    8
#define DKH   64
#define DFF   2048

// ---------------- scratch (device globals; no runtime allocation) ----------
__device__ float g_V[N_TOK * DM];
__device__ float g_tmp[N_TOK * DM];
__device__ float g_h1[N_TOK * DM];

// fp16 activation planes (hi only) and fp16 weights (hi only)
__device__ __half g_hb[N_TOK * DM];
__device__ __half g_cx[N_TOK * DM];
__device__ __half g_h1p[N_TOK * DM];
__device__ __half g_ffp[(size_t)N_TOK * DFF];
#define WOFF_Q  0
#define WOFF_K  (512 * 512)
#define WOFF_V  (2 * 512 * 512)
#define WOFF_O  (3 * 512 * 512)
#define WOFF_1  (4 * 512 * 512)
#define WOFF_2  (4 * 512 * 512 + 2048 * 512)
#define WTOT    (4 * 512 * 512 + 2 * 2048 * 512)
__device__ __half g_w[WTOT];

// attention (bf16): Q hi-only, K hi+lo, per-head [h][tok][64]; V^T [h][d][tok]
__device__ __nv_bfloat16 g_qs_hi[NH * N_TOK * DKH];
__device__ __nv_bfloat16 g_ks_hi[NH * N_TOK * DKH], g_ks_lo[NH * N_TOK * DKH];
__device__ __nv_bfloat16 g_vt[NH * DKH * N_TOK];
__device__ unsigned long long g_adjb[N_TOK * (N_TOK / 64)];

// epilogue output modes
#define OUT_F32   0
#define OUT_H16   1   // fp16 plane (activations)
#define OUT_QHEAD 2   // bf16 per-head hi-only, scaled
#define OUT_KHEAD 3   // bf16 per-head hi+lo

// ===================== low-level helpers ==================================
__device__ __forceinline__ uint32_t smem_u32(const void* p) {
    uint32_t a;
    asm("{ .reg .u64 t; cvta.to.shared.u64 t, %1; cvt.u32.u64 %0, t; }"
        : "=r"(a) : "l"(p));
    return a;
}
__device__ __forceinline__ void cp16(uint32_t dst, const void* src) {
    asm volatile("cp.async.cg.shared.global [%0], [%1], 16;" :: "r"(dst), "l"(src));
}
__device__ __forceinline__ void ldm_x4(uint32_t* r, uint32_t addr) {
    asm volatile("ldmatrix.sync.aligned.m8n8.x4.shared.b16 {%0,%1,%2,%3}, [%4];"
                 : "=r"(r[0]), "=r"(r[1]), "=r"(r[2]), "=r"(r[3]) : "r"(addr));
}
__device__ __forceinline__ void mma_bf16(float* d, const uint32_t* a, const uint32_t* b) {
    asm volatile("mma.sync.aligned.m16n8k16.row.col.f32.bf16.bf16.f32 "
                 "{%0,%1,%2,%3},{%4,%5,%6,%7},{%8,%9},{%0,%1,%2,%3};"
                 : "+f"(d[0]), "+f"(d[1]), "+f"(d[2]), "+f"(d[3])
                 : "r"(a[0]), "r"(a[1]), "r"(a[2]), "r"(a[3]),
                   "r"(b[0]), "r"(b[1]));
}
__device__ __forceinline__ void mma_fp16(float* d, const uint32_t* a, const uint32_t* b) {
    asm volatile("mma.sync.aligned.m16n8k16.row.col.f32.f16.f16.f32 "
                 "{%0,%1,%2,%3},{%4,%5,%6,%7},{%8,%9},{%0,%1,%2,%3};"
                 : "+f"(d[0]), "+f"(d[1]), "+f"(d[2]), "+f"(d[3])
                 : "r"(a[0]), "r"(a[1]), "r"(a[2]), "r"(a[3]),
                   "r"(b[0]), "r"(b[1]));
}
__device__ __forceinline__ float fexp2b(float s) {
    const float C1 = 12582904.0f;                 // 1.5*2^23 - 8
    float t  = s + C1;
    float v  = t - C1;
    float zf = s - v;
    int   zi = __float_as_int(t) - 0x4B400000;
    float p = fmaf(zf, 0.00961813f, 0.05550411f);
    p = fmaf(zf, p, 0.24022651f);
    p = fmaf(zf, p, 0.69314718f);
    p = fmaf(zf, p, 1.0f);
    return __int_as_float(__float_as_int(p) + (zi << 23));
}
__device__ __forceinline__ void split2b(float x, float y, uint32_t& hi, uint32_t& lo) {
    __nv_bfloat162 h = __floats2bfloat162_rn(x, y);
    float hx = __bfloat162float(h.x), hy = __bfloat162float(h.y);
    __nv_bfloat162 l = __floats2bfloat162_rn(x - hx, y - hy);
    hi = *reinterpret_cast<uint32_t*>(&h);
    lo = *reinterpret_cast<uint32_t*>(&l);
}
__device__ __forceinline__ uint32_t pack_b2(float x, float y) {
    __nv_bfloat162 h = __floats2bfloat162_rn(x, y);
    return *reinterpret_cast<uint32_t*>(&h);
}
__device__ __forceinline__ uint32_t pack_h2(float x, float y) {
    __half2 h = __floats2half2_rn(x, y);
    return *reinterpret_cast<uint32_t*>(&h);
}

// ===================== element-wise prep kernels ==========================
__global__ __launch_bounds__(256) void convert_h(const float* __restrict__ in,
                                                 __half* __restrict__ hi, int n)
{
    for (int i = (blockIdx.x * 256 + threadIdx.x) * 4; i < n; i += gridDim.x * 1024) {
        float4 v = *reinterpret_cast<const float4*>(in + i);
        *reinterpret_cast<uint32_t*>(hi + i)     = pack_h2(v.x, v.y);
        *reinterpret_cast<uint32_t*>(hi + i + 2) = pack_h2(v.z, v.w);
    }
}

// all 6 weights -> fp16, one launch
__global__ __launch_bounds__(256) void convert_w(const float* __restrict__ Wq,
                                                 const float* __restrict__ Wk,
                                                 const float* __restrict__ Wv,
                                                 const float* __restrict__ Wo,
                                                 const float* __restrict__ W1,
                                                 const float* __restrict__ W2,
                                                 __half* __restrict__ hi)
{
    const int WSQ = 512 * 512, WFF = 2048 * 512;
    for (int i = (blockIdx.x * 256 + threadIdx.x) * 4; i < WTOT; i += gridDim.x * 1024) {
        const float* src; int off;
        if (i < 4 * WSQ)            { int r = i / WSQ; off = i - r * WSQ;
                                      src = (r == 0) ? Wq : (r == 1) ? Wk : (r == 2) ? Wv : Wo; }
        else if (i < 4 * WSQ + WFF) { src = W1; off = i - 4 * WSQ; }
        else                        { src = W2; off = i - 4 * WSQ - WFF; }
        float4 v = *reinterpret_cast<const float4*>(src + off);
        *reinterpret_cast<uint32_t*>(hi + i)     = pack_h2(v.x, v.y);
        *reinterpret_cast<uint32_t*>(hi + i + 2) = pack_h2(v.z, v.w);
    }
}

__global__ __launch_bounds__(256) void convert_v_t(const float* __restrict__ V,
                                                   __nv_bfloat16* __restrict__ vt)
{
    __shared__ float sm[64][65];
    const int h = blockIdx.y, t0 = blockIdx.x * 64;
    const int tid = threadIdx.x;
    for (int i = tid; i < 1024; i += 256) {
        int r = i >> 4, c4 = (i & 15) * 4;
        float4 v = *reinterpret_cast<const float4*>(&V[(size_t)(t0 + r) * DM + h * DKH + c4]);
        sm[c4][r] = v.x; sm[c4 + 1][r] = v.y; sm[c4 + 2][r] = v.z; sm[c4 + 3][r] = v.w;
    }
    __syncthreads();
    for (int i = tid; i < 2048; i += 256) {
        int d = i >> 5, pr = i & 31;
        __nv_bfloat162 b = __floats2bfloat162_rn(sm[d][2 * pr], sm[d][2 * pr + 1]);
        *reinterpret_cast<__nv_bfloat162*>(
            vt + (size_t)h * (DKH * N_TOK) + (size_t)d * N_TOK + t0 + 2 * pr) = b;
    }
}

__global__ __launch_bounds__(256) void pack_adj(const int* __restrict__ adj,
                                                unsigned long long* __restrict__ bits)
{
    int gid = blockIdx.x * 256 + threadIdx.x;
    int r = gid >> 6, w = gid & 63;
    const int4* p = reinterpret_cast<const int4*>(adj + (size_t)r * N_TOK + w * 64);
    unsigned long long b = 0;
    #pragma unroll
    for (int i = 0; i < 16; i++) {
        int4 a = p[i];
        if (a.x) b |= 1ull << (i * 4 + 0);
        if (a.y) b |= 1ull << (i * 4 + 1);
        if (a.z) b |= 1ull << (i * 4 + 2);
        if (a.w) b |= 1ull << (i * 4 + 3);
    }
    if ((r >> 6) == w) b |= 1ull << (r & 63);
    bits[gid] = b;
}

// ===================== single-term fp16 GEMM (128x64 tile, pipelined) =====
// C = A * B^T + bias, pure fp16 operands, fp32 accumulate.
#define SROW 80
#define GS_AH 0
#define GS_BH 10240
#define GS_STAGE 15360
#define GEMM_SMEM (2 * GS_STAGE)

extern __shared__ __align__(128) uint8_t g_dyn[];

__device__ __forceinline__ void gemm_load_chunk(
    uint32_t sbase, const __half* gA, const __half* gB,
    int K, int c, int tid)
{
    const int u  = tid & 3;
    const int gk = c * 32 + u * 8;
    #pragma unroll
    for (int i = 0; i < 4; i++) {      // A: 128 rows
        const int row = (tid >> 2) + i * 32;
        cp16(sbase + GS_AH + (uint32_t)(row * SROW + u * 16),
             gA + (size_t)row * K + gk);
    }
    #pragma unroll
    for (int i = 0; i < 2; i++) {      // B: 64 rows
        const int row = (tid >> 2) + i * 32;
        cp16(sbase + GS_BH + (uint32_t)(row * SROW + u * 16),
             gB + (size_t)row * K + gk);
    }
    asm volatile("cp.async.commit_group;");
}

template <bool RELU>
__device__ __forceinline__ void gemm_mma_body(const __half* __restrict__ A,
                                              const __half* __restrict__ B,
                                              const float* __restrict__ bias,
                                              float* __restrict__ C,
                                              __half* __restrict__ Ph,
                                              __nv_bfloat16* __restrict__ H1,
                                              __nv_bfloat16* __restrict__ H2,
                                              float oscale,
                                              int Nn, int K, int mode)
{
    const int tid = threadIdx.x, lid = tid & 31, wid = tid >> 5;
    const int wm  = wid * 32;
    const int m0  = blockIdx.y * 128, n0 = blockIdx.x * 64;

    const uint32_t sb0 = smem_u32(g_dyn);
    const uint32_t sb[2] = {sb0, sb0 + GS_STAGE};

    const __half* gA = A + (size_t)m0 * K;
    const __half* gB = B + (size_t)n0 * K;

    const int a_row = lid & 15;
    const int a_sel = lid >> 4;
    const int b_row = ((lid >> 4) & 1) * 8 + (lid & 7);
    const int b_sel = (lid >> 3) & 1;

    float acc[2][8][4] = {};

    const int nch = K >> 5;
    gemm_load_chunk(sb[0], gA, gB, K, 0, tid);
    if (nch > 1)
        gemm_load_chunk(sb[1], gA, gB, K, 1, tid);

    for (int c = 0; c < nch; c++) {
        if (c == nch - 1) asm volatile("cp.async.wait_group 0;" ::: "memory");
        else              asm volatile("cp.async.wait_group 1;" ::: "memory");
        __syncthreads();

        const uint32_t st = sb[c & 1];
        #pragma unroll
        for (int ks = 0; ks < 2; ks++) {
            uint32_t ah[2][4];
            #pragma unroll
            for (int mg = 0; mg < 2; mg++) {
                const uint32_t aoff = (uint32_t)((wm + mg * 16 + a_row) * SROW
                                                 + (ks * 2 + a_sel) * 16);
                ldm_x4(ah[mg], st + GS_AH + aoff);
            }
            uint32_t bh[4][4];
            #pragma unroll
            for (int t = 0; t < 4; t++) {
                const uint32_t boff = (uint32_t)((t * 16 + b_row) * SROW
                                                 + (ks * 2 + b_sel) * 16);
                ldm_x4(bh[t], st + GS_BH + boff);
            }
            #pragma unroll
            for (int t = 0; t < 4; t++)
                #pragma unroll
                for (int mg = 0; mg < 2; mg++)
                    #pragma unroll
                    for (int t2 = 0; t2 < 2; t2++)
                        mma_fp16(acc[mg][t * 2 + t2], ah[mg], &bh[t][t2 * 2]);
        }
        __syncthreads();
        if (c + 2 < nch)
            gemm_load_chunk(sb[c & 1], gA, gB, K, c + 2, tid);
    }

    // epilogue
    const int cbase = n0 + (lid & 3) * 2;
    #pragma unroll
    for (int mg = 0; mg < 2; mg++) {
        const int rr0 = m0 + wm + mg * 16 + (lid >> 2);
        #pragma unroll
        for (int f = 0; f < 8; f++) {
            const int col = cbase + f * 8;
            const float bx = bias[col], by = bias[col + 1];
            float v00 = acc[mg][f][0] + bx, v01 = acc[mg][f][1] + by;
            float v10 = acc[mg][f][2] + bx, v11 = acc[mg][f][3] + by;
            if (RELU) {
                v00 = fmaxf(v00, 0.0f); v01 = fmaxf(v01, 0.0f);
                v10 = fmaxf(v10, 0.0f); v11 = fmaxf(v11, 0.0f);
            }
            if (mode == OUT_F32) {
                *reinterpret_cast<float2*>(C + (size_t)rr0 * Nn + col)       = make_float2(v00, v01);
                *reinterpret_cast<float2*>(C + (size_t)(rr0 + 8) * Nn + col) = make_float2(v10, v11);
            } else if (mode == OUT_H16) {
                *reinterpret_cast<uint32_t*>(Ph + (size_t)rr0 * Nn + col)       = pack_h2(v00, v01);
                *reinterpret_cast<uint32_t*>(Ph + (size_t)(rr0 + 8) * Nn + col) = pack_h2(v10, v11);
            } else if (mode == OUT_QHEAD) {
                const int hh = col >> 6, d = col & 63;
                const size_t base0 = (size_t)hh * (N_TOK * DKH) + (size_t)rr0 * DKH + d;
                *reinterpret_cast<uint32_t*>(H1 + base0)           = pack_b2(v00 * oscale, v01 * oscale);
                *reinterpret_cast<uint32_t*>(H1 + base0 + 8 * DKH) = pack_b2(v10 * oscale, v11 * oscale);
            } else {                             // OUT_KHEAD
                const int hh = col >> 6, d = col & 63;
                const size_t base0 = (size_t)hh * (N_TOK * DKH) + (size_t)rr0 * DKH + d;
                const size_t base1 = base0 + 8 * DKH;
                uint32_t h0, l0, h1, l1;
                split2b(v00, v01, h0, l0);
                split2b(v10, v11, h1, l1);
                *reinterpret_cast<uint32_t*>(H1 + base0) = h0;
                *reinterpret_cast<uint32_t*>(H2 + base0) = l0;
                *reinterpret_cast<uint32_t*>(H1 + base1) = h1;
                *reinterpret_cast<uint32_t*>(H2 + base1) = l1;
            }
        }
    }
}

template <bool RELU>
__global__ __launch_bounds__(128) void gemm_mma(const __half* __restrict__ A,
                                                const __half* __restrict__ B,
                                                const float* __restrict__ bias,
                                                float* C, __half* Ph,
                                                int Nn, int K, int mode)
{
    gemm_mma_body<RELU>(A, B, bias, C, Ph, nullptr, nullptr, 1.0f, Nn, K, mode);
}

__global__ __launch_bounds__(128) void gemm_mma_qkv(const __half* __restrict__ A,
                                                    const float* __restrict__ bq,
                                                    const float* __restrict__ bk,
                                                    const float* __restrict__ bv,
                                                    __nv_bfloat16* qhi,
                                                    __nv_bfloat16* khi, __nv_bfloat16* klo,
                                                    float* Vo, float qscale)
{
    if (blockIdx.z == 0)
        gemm_mma_body<false>(A, g_w + WOFF_Q, bq,
                             nullptr, nullptr, qhi, nullptr, qscale, DM, DM, OUT_QHEAD);
    else if (blockIdx.z == 1)
        gemm_mma_body<false>(A, g_w + WOFF_K, bk,
                             nullptr, nullptr, khi, klo, 1.0f, DM, DM, OUT_KHEAD);
    else
        gemm_mma_body<false>(A, g_w + WOFF_V, bv,
                             Vo, nullptr, nullptr, nullptr, 1.0f, DM, DM, OUT_F32);
}

// ===================== tensor-core flash attention (unchanged R14) ========
__global__ __launch_bounds__(256, 1) void attn_mma(
    const __nv_bfloat16* __restrict__ qhi,
    const __nv_bfloat16* __restrict__ khi, const __nv_bfloat16* __restrict__ klo,
    const __nv_bfloat16* __restrict__ vt,
    const unsigned long long* __restrict__ adjb,
    __half* __restrict__ cxh)
{
    __shared__ __align__(128) uint8_t s_khi[2 * 64 * SROW];
    __shared__ __align__(128) uint8_t s_klo[2 * 64 * SROW];
    __shared__ __align__(128) uint8_t s_vt [2 * 64 * SROW];

    const int tid = threadIdx.x, lid = tid & 31, wid = tid >> 5;
    const int h = blockIdx.y, q0 = blockIdx.x * 128;
    const int wm = wid * 16;
    const size_t hoff = (size_t)h * (N_TOK * DKH);

    const uint32_t skhi = smem_u32(s_khi), sklo = smem_u32(s_klo), svt = smem_u32(s_vt);

    uint32_t qa_h[4][4];
    const int rr0 = q0 + wm + (lid >> 2);
    {
        const int cc = (lid & 3) * 2;
        #pragma unroll
        for (int ks = 0; ks < 4; ks++) {
            const size_t o0 = hoff + (size_t)rr0 * 64 + ks * 16 + cc;
            const size_t o1 = hoff + (size_t)(rr0 + 8) * 64 + ks * 16 + cc;
            qa_h[ks][0] = *reinterpret_cast<const uint32_t*>(qhi + o0);
            qa_h[ks][1] = *reinterpret_cast<const uint32_t*>(qhi + o1);
            qa_h[ks][2] = *reinterpret_cast<const uint32_t*>(qhi + o0 + 8);
            qa_h[ks][3] = *reinterpret_cast<const uint32_t*>(qhi + o1 + 8);
        }
    }

    const int b_row = ((lid >> 4) & 1) * 8 + (lid & 7);
    const int b_sel = (lid >> 3) & 1;

    float o_acc[8][4] = {};
    float lsum0 = 0.0f, lsum1 = 0.0f;

    {
        #pragma unroll
        for (int i = 0; i < 2; i++) {
            const int idx = tid + i * 256;
            const int row = idx >> 3, ch = (idx >> 2) & 1, u = idx & 3;
            const uint32_t doff = (uint32_t)((ch * 64 + row) * SROW + u * 16);
            cp16(skhi + doff, khi + hoff + (size_t)row * 64 + ch * 32 + u * 8);
            cp16(sklo + doff, klo + hoff + (size_t)row * 64 + ch * 32 + u * 8);
            cp16(svt  + doff, vt  + hoff + (size_t)row * N_TOK + ch * 32 + u * 8);
        }
        asm volatile("cp.async.commit_group;");
    }

    for (int kb = 0; kb < N_TOK / 64; kb++) {
        asm volatile("cp.async.wait_group 0;" ::: "memory");
        __syncthreads();

        float sc[8][4] = {};
        #pragma unroll
        for (int ks = 0; ks < 4; ks++) {
            const uint32_t base = (uint32_t)(((ks >> 1) * 64 + b_row) * SROW
                                             + ((ks & 1) * 2 + b_sel) * 16);
            #pragma unroll
            for (int t = 0; t < 4; t++) {
                uint32_t bh[4], bl[4];
                ldm_x4(bh, skhi + base + t * 16 * SROW);
                ldm_x4(bl, sklo + base + t * 16 * SROW);
                #pragma unroll
                for (int t2 = 0; t2 < 2; t2++) {
                    float* d = sc[t * 2 + t2];
                    mma_bf16(d, qa_h[ks], &bh[t2 * 2]);
                    mma_bf16(d, qa_h[ks], &bl[t2 * 2]);
                }
            }
        }

        const unsigned long long w0 = adjb[(size_t)rr0 * 64 + kb];
        const unsigned long long w1 = adjb[(size_t)(rr0 + 8) * 64 + kb];
        uint32_t pa[4][4];
        #pragma unroll
        for (int f = 0; f < 8; f++) {
            const int cb = f * 8 + (lid & 3) * 2;
            const float s0 = ((w0 >> cb) & 1)       ? sc[f][0] : -102.0f;
            const float s1 = ((w0 >> (cb + 1)) & 1) ? sc[f][1] : -102.0f;
            const float s2 = ((w1 >> cb) & 1)       ? sc[f][2] : -102.0f;
            const float s3 = ((w1 >> (cb + 1)) & 1) ? sc[f][3] : -102.0f;
            const float p0 = fexp2b(s0), p1 = fexp2b(s1);
            const float p2 = fexp2b(s2), p3 = fexp2b(s3);
            lsum0 += p0 + p1; lsum1 += p2 + p3;
            const int j = f >> 1, oo = (f & 1) * 2;
            pa[j][oo]     = pack_b2(p0, p1);
            pa[j][oo + 1] = pack_b2(p2, p3);
        }

        #pragma unroll
        for (int ks = 0; ks < 4; ks++) {
            const uint32_t base = (uint32_t)(((ks >> 1) * 64 + b_row) * SROW
                                             + ((ks & 1) * 2 + b_sel) * 16);
            #pragma unroll
            for (int t = 0; t < 4; t++) {
                uint32_t bv[4];
                ldm_x4(bv, svt + base + t * 16 * SROW);
                mma_bf16(o_acc[t * 2],     pa[ks], &bv[0]);
                mma_bf16(o_acc[t * 2 + 1], pa[ks], &bv[2]);
            }
        }

        __syncthreads();
        if (kb < N_TOK / 64 - 1) {
            const int k0 = (kb + 1) * 64;
            #pragma unroll
            for (int i = 0; i < 2; i++) {
                const int idx = tid + i * 256;
                const int row = idx >> 3, ch = (idx >> 2) & 1, u = idx & 3;
                const uint32_t doff = (uint32_t)((ch * 64 + row) * SROW + u * 16);
                cp16(skhi + doff, khi + hoff + (size_t)(k0 + row) * 64 + ch * 32 + u * 8);
                cp16(sklo + doff, klo + hoff + (size_t)(k0 + row) * 64 + ch * 32 + u * 8);
                cp16(svt  + doff, vt  + hoff + (size_t)row * N_TOK + k0 + ch * 32 + u * 8);
            }
            asm volatile("cp.async.commit_group;");
        }
    }

    lsum0 += __shfl_xor_sync(0xffffffffu, lsum0, 1);
    lsum0 += __shfl_xor_sync(0xffffffffu, lsum0, 2);
    lsum1 += __shfl_xor_sync(0xffffffffu, lsum1, 1);
    lsum1 += __shfl_xor_sync(0xffffffffu, lsum1, 2);
    const float inv0 = 1.0f / lsum0, inv1 = 1.0f / lsum1;
    const int col0 = h * DKH + (lid & 3) * 2;
    #pragma unroll
    for (int f = 0; f < 8; f++) {
        const size_t a0 = (size_t)rr0 * DM + col0 + f * 8;
        const size_t a1 = (size_t)(rr0 + 8) * DM + col0 + f * 8;
        *reinterpret_cast<uint32_t*>(cxh + a0) = pack_h2(o_acc[f][0] * inv0, o_acc[f][1] * inv0);
        *reinterpret_cast<uint32_t*>(cxh + a1) = pack_h2(o_acc[f][2] * inv1, o_acc[f][3] * inv1);
    }
}

// ---------------------------------------------------------------------------
// out = LayerNorm(x + r) * g + b; optionally also fp16 plane
// ---------------------------------------------------------------------------
template <bool PLANES>
__global__ __launch_bounds__(128) void ln_kernel(const float* __restrict__ x,
                                                 const float* __restrict__ r,
                                                 const float* __restrict__ g,
                                                 const float* __restrict__ b,
                                                 float* __restrict__ out,
                                                 __half* __restrict__ ph)
{
    __shared__ float ws[4], ws2[4];
    const int row = blockIdx.x;
    const int tid = threadIdx.x;
    const int col = tid * 4;

    float4 xv = *reinterpret_cast<const float4*>(&x[(size_t)row * DM + col]);
    float4 rv = *reinterpret_cast<const float4*>(&r[(size_t)row * DM + col]);
    float v[4] = {xv.x + rv.x, xv.y + rv.y, xv.z + rv.z, xv.w + rv.w};

    float s = 0.0f, s2 = 0.0f;
    #pragma unroll
    for (int c = 0; c < 4; c++) { s += v[c]; s2 = fmaf(v[c], v[c], s2); }
    #pragma unroll
    for (int off = 16; off >= 1; off >>= 1) {
        s  += __shfl_xor_sync(0xffffffffu, s,  off);
        s2 += __shfl_xor_sync(0xffffffffu, s2, off);
    }
    const int wid = tid >> 5;
    if ((tid & 31) == 0) { ws[wid] = s; ws2[wid] = s2; }
    __syncthreads();
    const float S  = ws[0] + ws[1] + ws[2] + ws[3];
    const float S2 = ws2[0] + ws2[1] + ws2[2] + ws2[3];
    const float mean = S * (1.0f / DM);
    const float var  = S2 * (1.0f / DM) - mean * mean;
    const float rstd = rsqrtf(var + 1e-5f);

    float4 gv = *reinterpret_cast<const float4*>(&g[col]);
    float4 bv = *reinterpret_cast<const float4*>(&b[col]);
    float gr[4] = {gv.x, gv.y, gv.z, gv.w};
    float br[4] = {bv.x, bv.y, bv.z, bv.w};
    float4 ov; float* op = &ov.x;
    #pragma unroll
    for (int c = 0; c < 4; c++)
        op[c] = (v[c] - mean) * rstd * gr[c] + br[c];
    *reinterpret_cast<float4*>(&out[(size_t)row * DM + col]) = ov;
    if (PLANES) {
        *reinterpret_cast<uint32_t*>(ph + (size_t)row * DM + col)     = pack_h2(ov.x, ov.y);
        *reinterpret_cast<uint32_t*>(ph + (size_t)row * DM + col + 2) = pack_h2(ov.z, ov.w);
    }
}

// ---------------------------------------------------------------------------
extern "C" void kernel_launch(void* const* d_in, const int* in_sizes, int n_in,
                              void* d_out, int out_size)
{
    const float* h    = (const float*)d_in[0];
    const int*   adj  = (const int*)d_in[1];
    const float* Wq   = (const float*)d_in[2];
    const float* bq   = (const float*)d_in[3];
    const float* Wk   = (const float*)d_in[4];
    const float* bk   = (const float*)d_in[5];
    const float* Wv   = (const float*)d_in[6];
    const float* bv   = (const float*)d_in[7];
    const float* Wo   = (const float*)d_in[8];
    const float* bo   = (const float*)d_in[9];
    const float* W1   = (const float*)d_in[10];
    const float* b1   = (const float*)d_in[11];
    const float* W2   = (const float*)d_in[12];
    const float* b2   = (const float*)d_in[13];
    const float* ln1g = (const float*)d_in[14];
    const float* ln1b = (const float*)d_in[15];
    const float* ln2g = (const float*)d_in[16];
    const float* ln2b = (const float*)d_in[17];
    float* out = (float*)d_out;

    float *Vd, *tmp, *h1;
    cudaGetSymbolAddress((void**)&Vd,  g_V);
    cudaGetSymbolAddress((void**)&tmp, g_tmp);
    cudaGetSymbolAddress((void**)&h1,  g_h1);

    __half *hb, *cx, *h1p, *ffp, *w;
    __nv_bfloat16 *qs_hi, *ks_hi, *ks_lo, *vtp;
    unsigned long long* adjb;
    cudaGetSymbolAddress((void**)&hb,   g_hb);
    cudaGetSymbolAddress((void**)&cx,   g_cx);
    cudaGetSymbolAddress((void**)&h1p,  g_h1p);
    cudaGetSymbolAddress((void**)&ffp,  g_ffp);
    cudaGetSymbolAddress((void**)&w,    g_w);
    cudaGetSymbolAddress((void**)&qs_hi, g_qs_hi);
    cudaGetSymbolAddress((void**)&ks_hi, g_ks_hi);
    cudaGetSymbolAddress((void**)&ks_lo, g_ks_lo);
    cudaGetSymbolAddress((void**)&vtp,   g_vt);
    cudaGetSymbolAddress((void**)&adjb,  g_adjb);

    cudaFuncSetAttribute(gemm_mma_qkv,
                         cudaFuncAttributeMaxDynamicSharedMemorySize, GEMM_SMEM);
    cudaFuncSetAttribute(gemm_mma<false>,
                         cudaFuncAttributeMaxDynamicSharedMemorySize, GEMM_SMEM);
    cudaFuncSetAttribute(gemm_mma<true>,
                         cudaFuncAttributeMaxDynamicSharedMemorySize, GEMM_SMEM);

    const int ACT = N_TOK * DM;
    const float QSCALE = 1.4426950408889634f / 8.0f;   // log2(e)/sqrt(d_k)

    const dim3 blk(128);
    const dim3 gQKV(DM / 64, N_TOK / 128, 3);
    const dim3 gP(DM / 64, N_TOK / 128);
    const dim3 gF1(DFF / 64, N_TOK / 128);

    // launches ordered so attn_mma is the 6th launch (ncu -s 5 profiles it)
    pack_adj<<<(N_TOK * 64) / 256, 256>>>(adj, adjb);                       // 1
    convert_h<<<1024, 256>>>(h, hb, ACT);                                   // 2
    convert_w<<<2048, 256>>>(Wq, Wk, Wv, Wo, W1, W2, w);                    // 3
    gemm_mma_qkv<<<gQKV, blk, GEMM_SMEM>>>(hb, bq, bk, bv,                  // 4
                                           qs_hi, ks_hi, ks_lo, Vd, QSCALE);
    convert_v_t<<<dim3(N_TOK / 64, NH), 256>>>(Vd, vtp);                    // 5
    attn_mma<<<dim3(N_TOK / 128, NH), 256>>>(qs_hi, ks_hi, ks_lo,           // 6
                                             vtp, adjb, cx);
    gemm_mma<false><<<gP, blk, GEMM_SMEM>>>(cx, w + WOFF_O,
                                            bo, tmp, nullptr, DM, DM, OUT_F32);
    ln_kernel<true><<<N_TOK, 128>>>(h, tmp, ln1g, ln1b, h1, h1p);
    gemm_mma<true><<<gF1, blk, GEMM_SMEM>>>(h1p, w + WOFF_1,
                                            b1, nullptr, ffp, DFF, DM, OUT_H16);
    gemm_mma<false><<<gP, blk, GEMM_SMEM>>>(ffp, w + WOFF_2,
                                            b2, tmp, nullptr, DM, DFF, OUT_F32);
    ln_kernel<false><<<N_TOK, 128>>>(h1, tmp, ln2g, ln2b, out, nullptr);
}

// round 16
// speedup vs baseline: 1.6739x; 1.1439x over previous
#include <cuda_runtime.h>
#include <cuda_bf16.h>
#include <cuda_fp16.h>
#include <cstdint>

#define N_TOK 4096
#define DM    512
#define NH    8
#define DKH   64
#define DFF   2048

// ---------------- scratch (device globals; no runtime allocation) ----------
__device__ float g_V[N_TOK * DM];
__device__ float g_tmp[N_TOK * DM];
__device__ float g_h1[N_TOK * DM];

// fp16 activation planes and fp16 weights
__device__ __half g_hb[N_TOK * DM];
__device__ __half g_cx[N_TOK * DM];
__device__ __half g_h1p[N_TOK * DM];
__device__ __half g_ffp[(size_t)N_TOK * DFF];
#define WOFF_Q  0
#define WOFF_K  (512 * 512)
#define WOFF_V  (2 * 512 * 512)
#define WOFF_O  (3 * 512 * 512)
#define WOFF_1  (4 * 512 * 512)
#define WOFF_2  (4 * 512 * 512 + 2048 * 512)
#define WTOT    (4 * 512 * 512 + 2 * 2048 * 512)
__device__ __half g_w[WTOT];

// attention (fp16): Q (scaled), K per-head [h][tok][64]; V^T [h][d][tok]
__device__ __half g_qs[NH * N_TOK * DKH];
__device__ __half g_ks[NH * N_TOK * DKH];
__device__ __half g_vt[NH * DKH * N_TOK];
__device__ unsigned long long g_adjb[N_TOK * (N_TOK / 64)];

// epilogue output modes
#define OUT_F32    0
#define OUT_H16    1   // fp16 plane (activations)
#define OUT_HEAD16 2   // fp16 per-head, scaled

// ===================== low-level helpers ==================================
__device__ __forceinline__ uint32_t smem_u32(const void* p) {
    uint32_t a;
    asm("{ .reg .u64 t; cvta.to.shared.u64 t, %1; cvt.u32.u64 %0, t; }"
        : "=r"(a) : "l"(p));
    return a;
}
__device__ __forceinline__ void cp16(uint32_t dst, const void* src) {
    asm volatile("cp.async.cg.shared.global [%0], [%1], 16;" :: "r"(dst), "l"(src));
}
__device__ __forceinline__ void ldm_x4(uint32_t* r, uint32_t addr) {
    asm volatile("ldmatrix.sync.aligned.m8n8.x4.shared.b16 {%0,%1,%2,%3}, [%4];"
                 : "=r"(r[0]), "=r"(r[1]), "=r"(r[2]), "=r"(r[3]) : "r"(addr));
}
__device__ __forceinline__ void mma_fp16(float* d, const uint32_t* a, const uint32_t* b) {
    asm volatile("mma.sync.aligned.m16n8k16.row.col.f32.f16.f16.f32 "
                 "{%0,%1,%2,%3},{%4,%5,%6,%7},{%8,%9},{%0,%1,%2,%3};"
                 : "+f"(d[0]), "+f"(d[1]), "+f"(d[2]), "+f"(d[3])
                 : "r"(a[0]), "r"(a[1]), "r"(a[2]), "r"(a[3]),
                   "r"(b[0]), "r"(b[1]));
}
__device__ __forceinline__ float fexp2b(float s) {
    const float C1 = 12582904.0f;                 // 1.5*2^23 - 8
    float t  = s + C1;
    float v  = t - C1;
    float zf = s - v;
    int   zi = __float_as_int(t) - 0x4B400000;
    float p = fmaf(zf, 0.00961813f, 0.05550411f);
    p = fmaf(zf, p, 0.24022651f);
    p = fmaf(zf, p, 0.69314718f);
    p = fmaf(zf, p, 1.0f);
    return __int_as_float(__float_as_int(p) + (zi << 23));
}
__device__ __forceinline__ uint32_t pack_h2(float x, float y) {
    __half2 h = __floats2half2_rn(x, y);
    return *reinterpret_cast<uint32_t*>(&h);
}

// ===================== element-wise prep kernels ==========================
__global__ __launch_bounds__(256) void convert_h(const float* __restrict__ in,
                                                 __half* __restrict__ hi, int n)
{
    for (int i = (blockIdx.x * 256 + threadIdx.x) * 4; i < n; i += gridDim.x * 1024) {
        float4 v = *reinterpret_cast<const float4*>(in + i);
        *reinterpret_cast<uint32_t*>(hi + i)     = pack_h2(v.x, v.y);
        *reinterpret_cast<uint32_t*>(hi + i + 2) = pack_h2(v.z, v.w);
    }
}

// all 6 weights -> fp16, one launch
__global__ __launch_bounds__(256) void convert_w(const float* __restrict__ Wq,
                                                 const float* __restrict__ Wk,
                                                 const float* __restrict__ Wv,
                                                 const float* __restrict__ Wo,
                                                 const float* __restrict__ W1,
                                                 const float* __restrict__ W2,
                                                 __half* __restrict__ hi)
{
    const int WSQ = 512 * 512, WFF = 2048 * 512;
    for (int i = (blockIdx.x * 256 + threadIdx.x) * 4; i < WTOT; i += gridDim.x * 1024) {
        const float* src; int off;
        if (i < 4 * WSQ)            { int r = i / WSQ; off = i - r * WSQ;
                                      src = (r == 0) ? Wq : (r == 1) ? Wk : (r == 2) ? Wv : Wo; }
        else if (i < 4 * WSQ + WFF) { src = W1; off = i - 4 * WSQ; }
        else                        { src = W2; off = i - 4 * WSQ - WFF; }
        float4 v = *reinterpret_cast<const float4*>(src + off);
        *reinterpret_cast<uint32_t*>(hi + i)     = pack_h2(v.x, v.y);
        *reinterpret_cast<uint32_t*>(hi + i + 2) = pack_h2(v.z, v.w);
    }
}

__global__ __launch_bounds__(256) void convert_v_t(const float* __restrict__ V,
                                                   __half* __restrict__ vt)
{
    __shared__ float sm[64][65];
    const int h = blockIdx.y, t0 = blockIdx.x * 64;
    const int tid = threadIdx.x;
    for (int i = tid; i < 1024; i += 256) {
        int r = i >> 4, c4 = (i & 15) * 4;
        float4 v = *reinterpret_cast<const float4*>(&V[(size_t)(t0 + r) * DM + h * DKH + c4]);
        sm[c4][r] = v.x; sm[c4 + 1][r] = v.y; sm[c4 + 2][r] = v.z; sm[c4 + 3][r] = v.w;
    }
    __syncthreads();
    for (int i = tid; i < 2048; i += 256) {
        int d = i >> 5, pr = i & 31;
        *reinterpret_cast<uint32_t*>(
            vt + (size_t)h * (DKH * N_TOK) + (size_t)d * N_TOK + t0 + 2 * pr)
            = pack_h2(sm[d][2 * pr], sm[d][2 * pr + 1]);
    }
}

__global__ __launch_bounds__(256) void pack_adj(const int* __restrict__ adj,
                                                unsigned long long* __restrict__ bits)
{
    int gid = blockIdx.x * 256 + threadIdx.x;
    int r = gid >> 6, w = gid & 63;
    const int4* p = reinterpret_cast<const int4*>(adj + (size_t)r * N_TOK + w * 64);
    unsigned long long b = 0;
    #pragma unroll
    for (int i = 0; i < 16; i++) {
        int4 a = p[i];
        if (a.x) b |= 1ull << (i * 4 + 0);
        if (a.y) b |= 1ull << (i * 4 + 1);
        if (a.z) b |= 1ull << (i * 4 + 2);
        if (a.w) b |= 1ull << (i * 4 + 3);
    }
    if ((r >> 6) == w) b |= 1ull << (r & 63);
    bits[gid] = b;
}

// ===================== single-term fp16 GEMM (128x64 tile, pipelined) =====
#define SROW 80
#define GS_AH 0
#define GS_BH 10240
#define GS_STAGE 15360
#define GEMM_SMEM (2 * GS_STAGE)

extern __shared__ __align__(128) uint8_t g_dyn[];

__device__ __forceinline__ void gemm_load_chunk(
    uint32_t sbase, const __half* gA, const __half* gB,
    int K, int c, int tid)
{
    const int u  = tid & 3;
    const int gk = c * 32 + u * 8;
    #pragma unroll
    for (int i = 0; i < 4; i++) {      // A: 128 rows
        const int row = (tid >> 2) + i * 32;
        cp16(sbase + GS_AH + (uint32_t)(row * SROW + u * 16),
             gA + (size_t)row * K + gk);
    }
    #pragma unroll
    for (int i = 0; i < 2; i++) {      // B: 64 rows
        const int row = (tid >> 2) + i * 32;
        cp16(sbase + GS_BH + (uint32_t)(row * SROW + u * 16),
             gB + (size_t)row * K + gk);
    }
    asm volatile("cp.async.commit_group;");
}

template <bool RELU>
__device__ __forceinline__ void gemm_mma_body(const __half* __restrict__ A,
                                              const __half* __restrict__ B,
                                              const float* __restrict__ bias,
                                              float* __restrict__ C,
                                              __half* __restrict__ Ph,
                                              float oscale,
                                              int Nn, int K, int mode)
{
    const int tid = threadIdx.x, lid = tid & 31, wid = tid >> 5;
    const int wm  = wid * 32;
    const int m0  = blockIdx.y * 128, n0 = blockIdx.x * 64;

    const uint32_t sb0 = smem_u32(g_dyn);
    const uint32_t sb[2] = {sb0, sb0 + GS_STAGE};

    const __half* gA = A + (size_t)m0 * K;
    const __half* gB = B + (size_t)n0 * K;

    const int a_row = lid & 15;
    const int a_sel = lid >> 4;
    const int b_row = ((lid >> 4) & 1) * 8 + (lid & 7);
    const int b_sel = (lid >> 3) & 1;

    float acc[2][8][4] = {};

    const int nch = K >> 5;
    gemm_load_chunk(sb[0], gA, gB, K, 0, tid);
    if (nch > 1)
        gemm_load_chunk(sb[1], gA, gB, K, 1, tid);

    for (int c = 0; c < nch; c++) {
        if (c == nch - 1) asm volatile("cp.async.wait_group 0;" ::: "memory");
        else              asm volatile("cp.async.wait_group 1;" ::: "memory");
        __syncthreads();

        const uint32_t st = sb[c & 1];
        #pragma unroll
        for (int ks = 0; ks < 2; ks++) {
            uint32_t ah[2][4];
            #pragma unroll
            for (int mg = 0; mg < 2; mg++) {
                const uint32_t aoff = (uint32_t)((wm + mg * 16 + a_row) * SROW
                                                 + (ks * 2 + a_sel) * 16);
                ldm_x4(ah[mg], st + GS_AH + aoff);
            }
            uint32_t bh[4][4];
            #pragma unroll
            for (int t = 0; t < 4; t++) {
                const uint32_t boff = (uint32_t)((t * 16 + b_row) * SROW
                                                 + (ks * 2 + b_sel) * 16);
                ldm_x4(bh[t], st + GS_BH + boff);
            }
            #pragma unroll
            for (int t = 0; t < 4; t++)
                #pragma unroll
                for (int mg = 0; mg < 2; mg++)
                    #pragma unroll
                    for (int t2 = 0; t2 < 2; t2++)
                        mma_fp16(acc[mg][t * 2 + t2], ah[mg], &bh[t][t2 * 2]);
        }
        __syncthreads();
        if (c + 2 < nch)
            gemm_load_chunk(sb[c & 1], gA, gB, K, c + 2, tid);
    }

    // epilogue
    const int cbase = n0 + (lid & 3) * 2;
    #pragma unroll
    for (int mg = 0; mg < 2; mg++) {
        const int rr0 = m0 + wm + mg * 16 + (lid >> 2);
        #pragma unroll
        for (int f = 0; f < 8; f++) {
            const int col = cbase + f * 8;
            const float bx = bias[col], by = bias[col + 1];
            float v00 = acc[mg][f][0] + bx, v01 = acc[mg][f][1] + by;
            float v10 = acc[mg][f][2] + bx, v11 = acc[mg][f][3] + by;
            if (RELU) {
                v00 = fmaxf(v00, 0.0f); v01 = fmaxf(v01, 0.0f);
                v10 = fmaxf(v10, 0.0f); v11 = fmaxf(v11, 0.0f);
            }
            if (mode == OUT_F32) {
                *reinterpret_cast<float2*>(C + (size_t)rr0 * Nn + col)       = make_float2(v00, v01);
                *reinterpret_cast<float2*>(C + (size_t)(rr0 + 8) * Nn + col) = make_float2(v10, v11);
            } else if (mode == OUT_H16) {
                *reinterpret_cast<uint32_t*>(Ph + (size_t)rr0 * Nn + col)       = pack_h2(v00, v01);
                *reinterpret_cast<uint32_t*>(Ph + (size_t)(rr0 + 8) * Nn + col) = pack_h2(v10, v11);
            } else {   // OUT_HEAD16
                const int hh = col >> 6, d = col & 63;
                const size_t base0 = (size_t)hh * (N_TOK * DKH) + (size_t)rr0 * DKH + d;
                *reinterpret_cast<uint32_t*>(Ph + base0)           = pack_h2(v00 * oscale, v01 * oscale);
                *reinterpret_cast<uint32_t*>(Ph + base0 + 8 * DKH) = pack_h2(v10 * oscale, v11 * oscale);
            }
        }
    }
}

template <bool RELU>
__global__ __launch_bounds__(128) void gemm_mma(const __half* __restrict__ A,
                                                const __half* __restrict__ B,
                                                const float* __restrict__ bias,
                                                float* C, __half* Ph,
                                                int Nn, int K, int mode)
{
    gemm_mma_body<RELU>(A, B, bias, C, Ph, 1.0f, Nn, K, mode);
}

__global__ __launch_bounds__(128) void gemm_mma_qkv(const __half* __restrict__ A,
                                                    const float* __restrict__ bq,
                                                    const float* __restrict__ bk,
                                                    const float* __restrict__ bv,
                                                    __half* qs, __half* ks,
                                                    float* Vo, float qscale)
{
    if (blockIdx.z == 0)
        gemm_mma_body<false>(A, g_w + WOFF_Q, bq, nullptr, qs, qscale, DM, DM, OUT_HEAD16);
    else if (blockIdx.z == 1)
        gemm_mma_body<false>(A, g_w + WOFF_K, bk, nullptr, ks, 1.0f, DM, DM, OUT_HEAD16);
    else
        gemm_mma_body<false>(A, g_w + WOFF_V, bv, Vo, nullptr, 1.0f, DM, DM, OUT_F32);
}

// ===================== all-fp16 flash attention ===========================
// q-tile 128, 256 threads. Single-term fp16 QK, fp16 PV. cx -> fp16 plane.
__global__ __launch_bounds__(256, 1) void attn_mma(
    const __half* __restrict__ qs,
    const __half* __restrict__ ks,
    const __half* __restrict__ vt,
    const unsigned long long* __restrict__ adjb,
    __half* __restrict__ cxh)
{
    __shared__ __align__(128) uint8_t s_k[2 * 64 * SROW];
    __shared__ __align__(128) uint8_t s_v[2 * 64 * SROW];

    const int tid = threadIdx.x, lid = tid & 31, wid = tid >> 5;
    const int h = blockIdx.y, q0 = blockIdx.x * 128;
    const int wm = wid * 16;
    const size_t hoff = (size_t)h * (N_TOK * DKH);

    const uint32_t sk = smem_u32(s_k), sv = smem_u32(s_v);

    uint32_t qa[4][4];
    const int rr0 = q0 + wm + (lid >> 2);
    {
        const int cc = (lid & 3) * 2;
        #pragma unroll
        for (int ks4 = 0; ks4 < 4; ks4++) {
            const size_t o0 = hoff + (size_t)rr0 * 64 + ks4 * 16 + cc;
            const size_t o1 = hoff + (size_t)(rr0 + 8) * 64 + ks4 * 16 + cc;
            qa[ks4][0] = *reinterpret_cast<const uint32_t*>(qs + o0);
            qa[ks4][1] = *reinterpret_cast<const uint32_t*>(qs + o1);
            qa[ks4][2] = *reinterpret_cast<const uint32_t*>(qs + o0 + 8);
            qa[ks4][3] = *reinterpret_cast<const uint32_t*>(qs + o1 + 8);
        }
    }

    const int b_row = ((lid >> 4) & 1) * 8 + (lid & 7);
    const int b_sel = (lid >> 3) & 1;

    float o_acc[8][4] = {};
    float lsum0 = 0.0f, lsum1 = 0.0f;

    {
        #pragma unroll
        for (int i = 0; i < 2; i++) {
            const int idx = tid + i * 256;
            const int row = idx >> 3, ch = (idx >> 2) & 1, u = idx & 3;
            const uint32_t doff = (uint32_t)((ch * 64 + row) * SROW + u * 16);
            cp16(sk + doff, ks + hoff + (size_t)row * 64 + ch * 32 + u * 8);
            cp16(sv + doff, vt + hoff + (size_t)row * N_TOK + ch * 32 + u * 8);
        }
        asm volatile("cp.async.commit_group;");
    }

    for (int kb = 0; kb < N_TOK / 64; kb++) {
        asm volatile("cp.async.wait_group 0;" ::: "memory");
        __syncthreads();

        float sc[8][4] = {};
        #pragma unroll
        for (int ks4 = 0; ks4 < 4; ks4++) {
            const uint32_t base = (uint32_t)(((ks4 >> 1) * 64 + b_row) * SROW
                                             + ((ks4 & 1) * 2 + b_sel) * 16);
            #pragma unroll
            for (int t = 0; t < 4; t++) {
                uint32_t bh[4];
                ldm_x4(bh, sk + base + t * 16 * SROW);
                mma_fp16(sc[t * 2],     qa[ks4], &bh[0]);
                mma_fp16(sc[t * 2 + 1], qa[ks4], &bh[2]);
            }
        }

        const unsigned long long w0 = adjb[(size_t)rr0 * 64 + kb];
        const unsigned long long w1 = adjb[(size_t)(rr0 + 8) * 64 + kb];
        uint32_t pa[4][4];
        #pragma unroll
        for (int f = 0; f < 8; f++) {
            const int cb = f * 8 + (lid & 3) * 2;
            const float s0 = ((w0 >> cb) & 1)       ? sc[f][0] : -102.0f;
            const float s1 = ((w0 >> (cb + 1)) & 1) ? sc[f][1] : -102.0f;
            const float s2 = ((w1 >> cb) & 1)       ? sc[f][2] : -102.0f;
            const float s3 = ((w1 >> (cb + 1)) & 1) ? sc[f][3] : -102.0f;
            const float p0 = fexp2b(s0), p1 = fexp2b(s1);
            const float p2 = fexp2b(s2), p3 = fexp2b(s3);
            lsum0 += p0 + p1; lsum1 += p2 + p3;
            const int j = f >> 1, oo = (f & 1) * 2;
            pa[j][oo]     = pack_h2(p0, p1);
            pa[j][oo + 1] = pack_h2(p2, p3);
        }

        #pragma unroll
        for (int ks4 = 0; ks4 < 4; ks4++) {
            const uint32_t base = (uint32_t)(((ks4 >> 1) * 64 + b_row) * SROW
                                             + ((ks4 & 1) * 2 + b_sel) * 16);
            #pragma unroll
            for (int t = 0; t < 4; t++) {
                uint32_t bv[4];
                ldm_x4(bv, sv + base + t * 16 * SROW);
                mma_fp16(o_acc[t * 2],     pa[ks4], &bv[0]);
                mma_fp16(o_acc[t * 2 + 1], pa[ks4], &bv[2]);
            }
        }

        __syncthreads();
        if (kb < N_TOK / 64 - 1) {
            const int k0 = (kb + 1) * 64;
            #pragma unroll
            for (int i = 0; i < 2; i++) {
                const int idx = tid + i * 256;
                const int row = idx >> 3, ch = (idx >> 2) & 1, u = idx & 3;
                const uint32_t doff = (uint32_t)((ch * 64 + row) * SROW + u * 16);
                cp16(sk + doff, ks + hoff + (size_t)(k0 + row) * 64 + ch * 32 + u * 8);
                cp16(sv + doff, vt + hoff + (size_t)row * N_TOK + k0 + ch * 32 + u * 8);
            }
            asm volatile("cp.async.commit_group;");
        }
    }

    lsum0 += __shfl_xor_sync(0xffffffffu, lsum0, 1);
    lsum0 += __shfl_xor_sync(0xffffffffu, lsum0, 2);
    lsum1 += __shfl_xor_sync(0xffffffffu, lsum1, 1);
    lsum1 += __shfl_xor_sync(0xffffffffu, lsum1, 2);
    const float inv0 = 1.0f / lsum0, inv1 = 1.0f / lsum1;
    const int col0 = h * DKH + (lid & 3) * 2;
    #pragma unroll
    for (int f = 0; f < 8; f++) {
        const size_t a0 = (size_t)rr0 * DM + col0 + f * 8;
        const size_t a1 = (size_t)(rr0 + 8) * DM + col0 + f * 8;
        *reinterpret_cast<uint32_t*>(cxh + a0) = pack_h2(o_acc[f][0] * inv0, o_acc[f][1] * inv0);
        *reinterpret_cast<uint32_t*>(cxh + a1) = pack_h2(o_acc[f][2] * inv1, o_acc[f][3] * inv1);
    }
}

// ---------------------------------------------------------------------------
// out = LayerNorm(x + r) * g + b; optionally also fp16 plane
// ---------------------------------------------------------------------------
template <bool PLANES>
__global__ __launch_bounds__(128) void ln_kernel(const float* __restrict__ x,
                                                 const float* __restrict__ r,
                                                 const float* __restrict__ g,
                                                 const float* __restrict__ b,
                                                 float* __restrict__ out,
                                                 __half* __restrict__ ph)
{
    __shared__ float ws[4], ws2[4];
    const int row = blockIdx.x;
    const int tid = threadIdx.x;
    const int col = tid * 4;

    float4 xv = *reinterpret_cast<const float4*>(&x[(size_t)row * DM + col]);
    float4 rv = *reinterpret_cast<const float4*>(&r[(size_t)row * DM + col]);
    float v[4] = {xv.x + rv.x, xv.y + rv.y, xv.z + rv.z, xv.w + rv.w};

    float s = 0.0f, s2 = 0.0f;
    #pragma unroll
    for (int c = 0; c < 4; c++) { s += v[c]; s2 = fmaf(v[c], v[c], s2); }
    #pragma unroll
    for (int off = 16; off >= 1; off >>= 1) {
        s  += __shfl_xor_sync(0xffffffffu, s,  off);
        s2 += __shfl_xor_sync(0xffffffffu, s2, off);
    }
    const int wid = tid >> 5;
    if ((tid & 31) == 0) { ws[wid] = s; ws2[wid] = s2; }
    __syncthreads();
    const float S  = ws[0] + ws[1] + ws[2] + ws[3];
    const float S2 = ws2[0] + ws2[1] + ws2[2] + ws2[3];
    const float mean = S * (1.0f / DM);
    const float var  = S2 * (1.0f / DM) - mean * mean;
    const float rstd = rsqrtf(var + 1e-5f);

    float4 gv = *reinterpret_cast<const float4*>(&g[col]);
    float4 bv = *reinterpret_cast<const float4*>(&b[col]);
    float gr[4] = {gv.x, gv.y, gv.z, gv.w};
    float br[4] = {bv.x, bv.y, bv.z, bv.w};
    float4 ov; float* op = &ov.x;
    #pragma unroll
    for (int c = 0; c < 4; c++)
        op[c] = (v[c] - mean) * rstd * gr[c] + br[c];
    *reinterpret_cast<float4*>(&out[(size_t)row * DM + col]) = ov;
    if (PLANES) {
        *reinterpret_cast<uint32_t*>(ph + (size_t)row * DM + col)     = pack_h2(ov.x, ov.y);
        *reinterpret_cast<uint32_t*>(ph + (size_t)row * DM + col + 2) = pack_h2(ov.z, ov.w);
    }
}

// ---------------------------------------------------------------------------
extern "C" void kernel_launch(void* const* d_in, const int* in_sizes, int n_in,
                              void* d_out, int out_size)
{
    const float* h    = (const float*)d_in[0];
    const int*   adj  = (const int*)d_in[1];
    const float* Wq   = (const float*)d_in[2];
    const float* bq   = (const float*)d_in[3];
    const float* Wk   = (const float*)d_in[4];
    const float* bk   = (const float*)d_in[5];
    const float* Wv   = (const float*)d_in[6];
    const float* bv   = (const float*)d_in[7];
    const float* Wo   = (const float*)d_in[8];
    const float* bo   = (const float*)d_in[9];
    const float* W1   = (const float*)d_in[10];
    const float* b1   = (const float*)d_in[11];
    const float* W2   = (const float*)d_in[12];
    const float* b2   = (const float*)d_in[13];
    const float* ln1g = (const float*)d_in[14];
    const float* ln1b = (const float*)d_in[15];
    const float* ln2g = (const float*)d_in[16];
    const float* ln2b = (const float*)d_in[17];
    float* out = (float*)d_out;

    float *Vd, *tmp, *h1;
    cudaGetSymbolAddress((void**)&Vd,  g_V);
    cudaGetSymbolAddress((void**)&tmp, g_tmp);
    cudaGetSymbolAddress((void**)&h1,  g_h1);

    __half *hb, *cx, *h1p, *ffp, *w, *qsp, *ksp, *vtp;
    unsigned long long* adjb;
    cudaGetSymbolAddress((void**)&hb,   g_hb);
    cudaGetSymbolAddress((void**)&cx,   g_cx);
    cudaGetSymbolAddress((void**)&h1p,  g_h1p);
    cudaGetSymbolAddress((void**)&ffp,  g_ffp);
    cudaGetSymbolAddress((void**)&w,    g_w);
    cudaGetSymbolAddress((void**)&qsp,  g_qs);
    cudaGetSymbolAddress((void**)&ksp,  g_ks);
    cudaGetSymbolAddress((void**)&vtp,  g_vt);
    cudaGetSymbolAddress((void**)&adjb, g_adjb);

    cudaFuncSetAttribute(gemm_mma_qkv,
                         cudaFuncAttributeMaxDynamicSharedMemorySize, GEMM_SMEM);
    cudaFuncSetAttribute(gemm_mma<false>,
                         cudaFuncAttributeMaxDynamicSharedMemorySize, GEMM_SMEM);
    cudaFuncSetAttribute(gemm_mma<true>,
                         cudaFuncAttributeMaxDynamicSharedMemorySize, GEMM_SMEM);

    const int ACT = N_TOK * DM;
    const float QSCALE = 1.4426950408889634f / 8.0f;   // log2(e)/sqrt(d_k)

    const dim3 blk(128);
    const dim3 gQKV(DM / 64, N_TOK / 128, 3);
    const dim3 gP(DM / 64, N_TOK / 128);
    const dim3 gF1(DFF / 64, N_TOK / 128);

    // launches ordered so attn_mma is the 6th launch (ncu -s 5 profiles it)
    pack_adj<<<(N_TOK * 64) / 256, 256>>>(adj, adjb);                       // 1
    convert_h<<<1024, 256>>>(h, hb, ACT);                                   // 2
    convert_w<<<2048, 256>>>(Wq, Wk, Wv, Wo, W1, W2, w);                    // 3
    gemm_mma_qkv<<<gQKV, blk, GEMM_SMEM>>>(hb, bq, bk, bv,                  // 4
                                           qsp, ksp, Vd, QSCALE);
    convert_v_t<<<dim3(N_TOK / 64, NH), 256>>>(Vd, vtp);                    // 5
    attn_mma<<<dim3(N_TOK / 128, NH), 256>>>(qsp, ksp, vtp, adjb, cx);      // 6
    gemm_mma<false><<<gP, blk, GEMM_SMEM>>>(cx, w + WOFF_O,
                                            bo, tmp, nullptr, DM, DM, OUT_F32);
    ln_kernel<true><<<N_TOK, 128>>>(h, tmp, ln1g, ln1b, h1, h1p);
    gemm_mma<true><<<gF1, blk, GEMM_SMEM>>>(h1p, w + WOFF_1,
                                            b1, nullptr, ffp, DFF, DM, OUT_H16);
    gemm_mma<false><<<gP, blk, GEMM_SMEM>>>(ffp, w + WOFF_2,
                                            b2, tmp, nullptr, DM, DFF, OUT_F32);
    ln_kernel<false><<<N_TOK, 128>>>(h1, tmp, ln2g, ln2b, out, nullptr);
}